// round 1
// baseline (speedup 1.0000x reference)
#include <cuda_runtime.h>
#include <math.h>

// ---- problem dims ----
#define BATCH  8
#define FDIM   512
#define KDIM   64
#define EDIM   128
#define WWIN   16
#define TPP    4
#define SHIFTT 2
#define NHEAD  4
#define LWIN   64      // TPP*WWIN
#define FFI    128     // FDIM/TPP
#define NWIN   4       // KDIM/WWIN
#define DHEAD  32
#define QK_SCALE 0.17677669529663687f  // (EDIM/NHEAD)^-0.5
#define LN_EPS 1e-5f

// ---- kernel1 shared memory layout (floats) ----
#define XN_OFF 0                 // 64*129  : xn, later attn-out
#define QS_OFF (64*129)          // 64*129  : q (pre-scaled)
#define KS_OFF (2*64*129)        // 64*129  : k, later proj-out staging
#define VS_OFF (3*64*129)        // 64*129  : v
#define WT_OFF (4*64*129)        // 128*128 : weight tile, also scores (64*65)
#define SM1_FLOATS (4*64*129 + 128*128)
#define SM1_BYTES  (SM1_FLOATS * 4)

// ---- kernel2 shared memory layout (floats) ----
#define XS_OFF2  0               // 64*129 : LN2(x), later h staging
#define W1_OFF2  (64*129)        // 32*128 : fc1 weight tile
#define AS_OFF2  (64*129 + 32*128)           // 64*33 : gelu(fc1) tile
#define W2_OFF2  (64*129 + 32*128 + 64*33)   // 128*33 : fc2 weight tile
#define SM2_FLOATS (64*129 + 32*128 + 64*33 + 128*33)
#define SM2_BYTES  (SM2_FLOATS * 4)

// ============================================================================
// Kernel 1: shift + window partition + LN1 + QKV + masked attention + proj
//           + reverse roll + window reverse + residual.  One block per window.
// ============================================================================
__global__ __launch_bounds__(512, 1)
void attn_kernel(const float* __restrict__ x,
                 const float* __restrict__ qkv_w,
                 const float* __restrict__ qkv_b,
                 const float* __restrict__ proj_w,
                 const float* __restrict__ proj_b,
                 const float* __restrict__ ln1_s,
                 const float* __restrict__ ln1_b,
                 float* __restrict__ out)
{
    extern __shared__ float sm[];
    float* XN = sm + XN_OFF;
    float* QS = sm + QS_OFF;
    float* KS = sm + KS_OFF;
    float* VS = sm + VS_OFF;
    float* WT = sm + WT_OFF;
    float* S  = sm + WT_OFF;   // scores alias (64*65 <= 128*128)

    const int tid = threadIdx.x;
    const int n   = blockIdx.x;
    const int wi  = n & (NWIN - 1);          // window along K
    const int fi  = (n >> 2) & (FFI - 1);    // frame-group
    const int b   = n >> 9;                  // batch

    // ---------------- Phase A: gather (roll -SHIFT) + LayerNorm1 -------------
    {
        const int l = tid >> 3;          // token 0..63
        const int g = tid & 7;           // 8 threads per token
        const int tp = l >> 4;
        const int w  = l & 15;
        int srcf = fi * TPP + tp + SHIFTT;
        if (srcf >= FDIM) srcf -= FDIM;
        const int kk = wi * WWIN + w;
        const float* xp = x + (((size_t)b * FDIM + srcf) * KDIM + kk) * EDIM + g * 16;

        float v[16];
#pragma unroll
        for (int i = 0; i < 4; i++) {
            float4 t = reinterpret_cast<const float4*>(xp)[i];
            v[4*i+0] = t.x; v[4*i+1] = t.y; v[4*i+2] = t.z; v[4*i+3] = t.w;
        }
        float s1 = 0.f, s2 = 0.f;
#pragma unroll
        for (int i = 0; i < 16; i++) { s1 += v[i]; s2 += v[i]*v[i]; }
#pragma unroll
        for (int d = 1; d < 8; d <<= 1) {
            s1 += __shfl_xor_sync(0xffffffffu, s1, d, 8);
            s2 += __shfl_xor_sync(0xffffffffu, s2, d, 8);
        }
        const float mean = s1 * (1.f / 128.f);
        const float var  = s2 * (1.f / 128.f) - mean * mean;
        const float rstd = rsqrtf(var + LN_EPS);
#pragma unroll
        for (int i = 0; i < 16; i++) {
            const int c = g * 16 + i;
            XN[l * 129 + c] = (v[i] - mean) * rstd * ln1_s[c] + ln1_b[c];
        }
    }
    __syncthreads();

    // ---------------- Phase B: QKV GEMM (64x384x128), 3 tiles of 128 rows ----
    {
        const int l0 = tid & 15;   // l = l0 + 16*a
        const int m0 = tid >> 4;   // m = m0 + 32*bm (within tile)
        for (int mt = 0; mt < 3 * EDIM; mt += 128) {
            const float4* src = reinterpret_cast<const float4*>(qkv_w + (size_t)mt * EDIM);
            float4* dst = reinterpret_cast<float4*>(WT);
#pragma unroll
            for (int i = 0; i < 8; i++) dst[tid + 512 * i] = src[tid + 512 * i];
            __syncthreads();

            float acc[4][4];
#pragma unroll
            for (int a = 0; a < 4; a++)
#pragma unroll
                for (int bm = 0; bm < 4; bm++) acc[a][bm] = 0.f;

#pragma unroll 4
            for (int c = 0; c < 128; c++) {
                float xv[4], wv[4];
#pragma unroll
                for (int a = 0; a < 4; a++)  xv[a]  = XN[(l0 + 16*a) * 129 + c];
#pragma unroll
                for (int bm = 0; bm < 4; bm++) wv[bm] = WT[(m0 + 32*bm) * 128 + c];
#pragma unroll
                for (int a = 0; a < 4; a++)
#pragma unroll
                    for (int bm = 0; bm < 4; bm++)
                        acc[a][bm] = fmaf(xv[a], wv[bm], acc[a][bm]);
            }
#pragma unroll
            for (int a = 0; a < 4; a++) {
                const int l = l0 + 16 * a;
#pragma unroll
                for (int bm = 0; bm < 4; bm++) {
                    const int m = mt + m0 + 32 * bm;
                    const float val = acc[a][bm] + qkv_b[m];
                    if (m < 128)          QS[l * 129 + m]       = val * QK_SCALE;
                    else if (m < 256)     KS[l * 129 + (m-128)] = val;
                    else                  VS[l * 129 + (m-256)] = val;
                }
            }
            __syncthreads();
        }
    }

    // ---------------- Phase C: attention, head by head ----------------------
    const bool maskwin = (fi == FFI - 1);
    for (int h = 0; h < NHEAD; h++) {
        // scores  s[i][j] = q[i]·k[j]   (q pre-scaled)
        {
            const int i  = tid & 63;
            const int jg = tid >> 6;    // 0..7
            float qreg[DHEAD];
#pragma unroll
            for (int d = 0; d < DHEAD; d++) qreg[d] = QS[i * 129 + h * DHEAD + d];
#pragma unroll
            for (int jj = 0; jj < 8; jj++) {
                const int j = jg * 8 + jj;
                float acc = 0.f;
#pragma unroll
                for (int d = 0; d < DHEAD; d++)
                    acc = fmaf(qreg[d], KS[j * 129 + h * DHEAD + d], acc);
                if (maskwin && ((i < 32) != (j < 32))) acc = 0.f;  // mask multiply
                if (acc == 0.f) acc = -10000.f;                    // masked_fill
                S[i * 65 + j] = acc;
            }
        }
        __syncthreads();
        // softmax over rows
        {
            const int i = tid >> 3;
            const int g = tid & 7;
            float e[8];
            float mx = -3.4e38f;
#pragma unroll
            for (int jj = 0; jj < 8; jj++) {
                e[jj] = S[i * 65 + g + 8 * jj];
                mx = fmaxf(mx, e[jj]);
            }
#pragma unroll
            for (int d = 1; d < 8; d <<= 1)
                mx = fmaxf(mx, __shfl_xor_sync(0xffffffffu, mx, d, 8));
            float ssum = 0.f;
#pragma unroll
            for (int jj = 0; jj < 8; jj++) { e[jj] = __expf(e[jj] - mx); ssum += e[jj]; }
#pragma unroll
            for (int d = 1; d < 8; d <<= 1)
                ssum += __shfl_xor_sync(0xffffffffu, ssum, d, 8);
            const float inv = 1.f / ssum;
#pragma unroll
            for (int jj = 0; jj < 8; jj++) S[i * 65 + g + 8 * jj] = e[jj] * inv;
        }
        __syncthreads();
        // PV: attnout[i][h*32+d] = sum_j s[i][j] * v[j][h*32+d]  -> into XN
        {
            const int d  = tid & 31;
            const int ig = tid >> 5;    // 0..15
            float acc[4] = {0.f, 0.f, 0.f, 0.f};
#pragma unroll 4
            for (int j = 0; j < LWIN; j++) {
                const float vv = VS[j * 129 + h * DHEAD + d];
#pragma unroll
                for (int ii = 0; ii < 4; ii++)
                    acc[ii] = fmaf(S[(ig * 4 + ii) * 65 + j], vv, acc[ii]);
            }
#pragma unroll
            for (int ii = 0; ii < 4; ii++)
                XN[(ig * 4 + ii) * 129 + h * DHEAD + d] = acc[ii];
        }
        __syncthreads();
    }

    // ---------------- Phase D: proj (64x128x128) -> KS staging ---------------
    {
        const float4* src = reinterpret_cast<const float4*>(proj_w);
        float4* dst = reinterpret_cast<float4*>(WT);
#pragma unroll
        for (int i = 0; i < 8; i++) dst[tid + 512 * i] = src[tid + 512 * i];
        __syncthreads();

        const int l0 = tid & 15;
        const int m0 = tid >> 4;
        float acc[4][4];
#pragma unroll
        for (int a = 0; a < 4; a++)
#pragma unroll
            for (int bm = 0; bm < 4; bm++) acc[a][bm] = 0.f;
#pragma unroll 4
        for (int c = 0; c < 128; c++) {
            float xv[4], wv[4];
#pragma unroll
            for (int a = 0; a < 4; a++)  xv[a]  = XN[(l0 + 16*a) * 129 + c];
#pragma unroll
            for (int bm = 0; bm < 4; bm++) wv[bm] = WT[(m0 + 32*bm) * 128 + c];
#pragma unroll
            for (int a = 0; a < 4; a++)
#pragma unroll
                for (int bm = 0; bm < 4; bm++)
                    acc[a][bm] = fmaf(xv[a], wv[bm], acc[a][bm]);
        }
        __syncthreads();
#pragma unroll
        for (int a = 0; a < 4; a++)
#pragma unroll
            for (int bm = 0; bm < 4; bm++) {
                const int m = m0 + 32 * bm;
                KS[(l0 + 16*a) * 129 + m] = acc[a][bm] + proj_b[m];
            }
    }
    __syncthreads();

    // ---------------- Phase E: roll(+SHIFT on L) + window reverse + residual -
    {
        const int lp = tid >> 3;            // destination token in window
        const int g  = tid & 7;
        const int tp = lp >> 4;
        const int w  = lp & 15;
        const int lsrc = (lp - SHIFTT + LWIN) & (LWIN - 1);
        const int frame = fi * TPP + tp;    // NOT shifted (shortcut layout)
        const int kk = wi * WWIN + w;
        const size_t base = (((size_t)b * FDIM + frame) * KDIM + kk) * EDIM + g * 16;
        const float* xp = x + base;
        float* op = out + base;
#pragma unroll
        for (int i = 0; i < 4; i++) {
            float4 t = reinterpret_cast<const float4*>(xp)[i];
            const int c = g * 16 + 4 * i;
            t.x += KS[lsrc * 129 + c + 0];
            t.y += KS[lsrc * 129 + c + 1];
            t.z += KS[lsrc * 129 + c + 2];
            t.w += KS[lsrc * 129 + c + 3];
            reinterpret_cast<float4*>(op)[i] = t;
        }
    }
}

// ============================================================================
// Kernel 2: LN2 + fc1 + exact GELU + fc2 + residual.  64 tokens per block.
// Reads/writes d_out in place (block-local tokens only).
// ============================================================================
__global__ __launch_bounds__(256, 3)
void mlp_kernel(float* __restrict__ io,
                const float* __restrict__ ln2_s,
                const float* __restrict__ ln2_b,
                const float* __restrict__ fc1_w,
                const float* __restrict__ fc1_b,
                const float* __restrict__ fc2_w,
                const float* __restrict__ fc2_b)
{
    extern __shared__ float sm[];
    float* XS  = sm + XS_OFF2;   // 64*129, later h staging
    float* W1T = sm + W1_OFF2;   // 32*128
    float* AS  = sm + AS_OFF2;   // 64*33
    float* W2T = sm + W2_OFF2;   // 128*33

    const int tid = threadIdx.x;
    const size_t tok0 = (size_t)blockIdx.x * 64;

    // ---------------- LN2 ----------------------------------------------------
    {
        const int l = tid >> 2;      // token 0..63
        const int q = tid & 3;       // 4 threads/token, 32 floats each
        const float* xp = io + (tok0 + l) * EDIM + q * 32;
        float v[32];
#pragma unroll
        for (int i = 0; i < 8; i++) {
            float4 t = reinterpret_cast<const float4*>(xp)[i];
            v[4*i+0] = t.x; v[4*i+1] = t.y; v[4*i+2] = t.z; v[4*i+3] = t.w;
        }
        float s1 = 0.f, s2 = 0.f;
#pragma unroll
        for (int i = 0; i < 32; i++) { s1 += v[i]; s2 += v[i]*v[i]; }
#pragma unroll
        for (int d = 1; d < 4; d <<= 1) {
            s1 += __shfl_xor_sync(0xffffffffu, s1, d, 4);
            s2 += __shfl_xor_sync(0xffffffffu, s2, d, 4);
        }
        const float mean = s1 * (1.f / 128.f);
        const float var  = s2 * (1.f / 128.f) - mean * mean;
        const float rstd = rsqrtf(var + LN_EPS);
#pragma unroll
        for (int i = 0; i < 32; i++) {
            const int c = q * 32 + i;
            XS[l * 129 + c] = (v[i] - mean) * rstd * ln2_s[c] + ln2_b[c];
        }
    }
    __syncthreads();

    // h accumulators: thread owns (l0+16*il, c0+16*ic), 4x8
    const int l0 = tid & 15;
    const int c0 = tid >> 4;     // 0..15
    float hacc[4][8];
#pragma unroll
    for (int il = 0; il < 4; il++)
#pragma unroll
        for (int ic = 0; ic < 8; ic++) hacc[il][ic] = 0.f;

    for (int mt = 0; mt < 4 * EDIM; mt += 32) {
        // load fc1 tile (32x128) and fc2 tile (128x32)
        {
            const float4* s1p = reinterpret_cast<const float4*>(fc1_w + (size_t)mt * EDIM);
            float4* d1 = reinterpret_cast<float4*>(W1T);
#pragma unroll
            for (int i = 0; i < 4; i++) d1[tid + 256 * i] = s1p[tid + 256 * i];
#pragma unroll
            for (int i = 0; i < 4; i++) {
                const int idx = tid + 256 * i;      // 0..1023
                const int c2  = idx >> 3;
                const int mq  = idx & 7;
                float4 t = *reinterpret_cast<const float4*>(fc2_w + (size_t)c2 * 512 + mt + mq * 4);
                W2T[c2 * 33 + mq * 4 + 0] = t.x;
                W2T[c2 * 33 + mq * 4 + 1] = t.y;
                W2T[c2 * 33 + mq * 4 + 2] = t.z;
                W2T[c2 * 33 + mq * 4 + 3] = t.w;
            }
        }
        __syncthreads();
        // fc1 + gelu -> AS (64 tokens x 32 m)
        {
            const int l  = tid & 63;
            const int mg = tid >> 6;   // 0..3
            float acc[8];
#pragma unroll
            for (int mi = 0; mi < 8; mi++) acc[mi] = 0.f;
#pragma unroll 4
            for (int cc = 0; cc < 128; cc++) {
                const float xv = XS[l * 129 + cc];
#pragma unroll
                for (int mi = 0; mi < 8; mi++)
                    acc[mi] = fmaf(xv, W1T[(mi * 4 + mg) * 128 + cc], acc[mi]);
            }
#pragma unroll
            for (int mi = 0; mi < 8; mi++) {
                const int m = mi * 4 + mg;
                float vv = acc[mi] + fc1_b[mt + m];
                vv = 0.5f * vv * (1.f + erff(vv * 0.70710678118654752f));
                AS[l * 33 + m] = vv;
            }
        }
        __syncthreads();
        // fc2 partial accumulate into registers
        {
#pragma unroll 4
            for (int m = 0; m < 32; m++) {
                float av[4], wv[8];
#pragma unroll
                for (int il = 0; il < 4; il++) av[il] = AS[(l0 + 16*il) * 33 + m];
#pragma unroll
                for (int ic = 0; ic < 8; ic++) wv[ic] = W2T[(c0 + 16*ic) * 33 + m];
#pragma unroll
                for (int il = 0; il < 4; il++)
#pragma unroll
                    for (int ic = 0; ic < 8; ic++)
                        hacc[il][ic] = fmaf(av[il], wv[ic], hacc[il][ic]);
            }
        }
        __syncthreads();
    }

    // stage h (+fc2 bias) into XS, then coalesced residual add
#pragma unroll
    for (int il = 0; il < 4; il++)
#pragma unroll
        for (int ic = 0; ic < 8; ic++)
            XS[(l0 + 16*il) * 129 + (c0 + 16*ic)] = hacc[il][ic] + fc2_b[c0 + 16*ic];
    __syncthreads();
    {
        const int l = tid >> 2;
        const int q = tid & 3;
        float* iop = io + (tok0 + l) * EDIM + q * 32;
#pragma unroll
        for (int i = 0; i < 8; i++) {
            float4 t = reinterpret_cast<const float4*>(iop)[i];
            const int cc = q * 32 + i * 4;
            t.x += XS[l * 129 + cc + 0];
            t.y += XS[l * 129 + cc + 1];
            t.z += XS[l * 129 + cc + 2];
            t.w += XS[l * 129 + cc + 3];
            reinterpret_cast<float4*>(iop)[i] = t;
        }
    }
}

// ============================================================================
extern "C" void kernel_launch(void* const* d_in, const int* in_sizes, int n_in,
                              void* d_out, int out_size)
{
    const float* x      = (const float*)d_in[0];
    const float* qkv_w  = (const float*)d_in[1];
    const float* qkv_b  = (const float*)d_in[2];
    const float* proj_w = (const float*)d_in[3];
    const float* proj_b = (const float*)d_in[4];
    const float* ln1_s  = (const float*)d_in[5];
    const float* ln1_b  = (const float*)d_in[6];
    const float* ln2_s  = (const float*)d_in[7];
    const float* ln2_b  = (const float*)d_in[8];
    const float* fc1_w  = (const float*)d_in[9];
    const float* fc1_b  = (const float*)d_in[10];
    const float* fc2_w  = (const float*)d_in[11];
    const float* fc2_b  = (const float*)d_in[12];
    float* out = (float*)d_out;

    cudaFuncSetAttribute(attn_kernel, cudaFuncAttributeMaxDynamicSharedMemorySize, SM1_BYTES);
    cudaFuncSetAttribute(mlp_kernel,  cudaFuncAttributeMaxDynamicSharedMemorySize, SM2_BYTES);

    const int nwindows = BATCH * FFI * NWIN;           // 4096
    attn_kernel<<<nwindows, 512, SM1_BYTES>>>(x, qkv_w, qkv_b, proj_w, proj_b,
                                              ln1_s, ln1_b, out);
    const int ntok_blocks = (BATCH * FDIM * KDIM) / 64; // 4096
    mlp_kernel<<<ntok_blocks, 256, SM2_BYTES>>>(out, ln2_s, ln2_b,
                                                fc1_w, fc1_b, fc2_w, fc2_b);
}

// round 4
// speedup vs baseline: 4.0576x; 4.0576x over previous
#include <cuda_runtime.h>
#include <cuda_bf16.h>
#include <math.h>
#include <stdint.h>

#define BATCH  8
#define FDIM   512
#define KDIM   64
#define EDIM   128
#define NHEAD  4
#define LWIN   64
#define FFI    128
#define NWIN   4
#define QK_SCALE 0.17677669529663687f
#define LN_EPS 1e-5f

__device__ __nv_bfloat16 g_wqkv[384 * 128];
__device__ __nv_bfloat16 g_wproj[128 * 128];
__device__ __nv_bfloat16 g_wfc1[512 * 128];
__device__ __nv_bfloat16 g_wfc2[128 * 512];

__device__ __forceinline__ uint32_t sa(const void* p) {
    return (uint32_t)__cvta_generic_to_shared(p);
}
__device__ __forceinline__ void ldmx4(uint32_t (&r)[4], uint32_t a) {
    asm volatile("ldmatrix.sync.aligned.m8n8.x4.shared.b16 {%0,%1,%2,%3}, [%4];"
                 : "=r"(r[0]), "=r"(r[1]), "=r"(r[2]), "=r"(r[3]) : "r"(a));
}
__device__ __forceinline__ void ldmx2(uint32_t (&r)[2], uint32_t a) {
    asm volatile("ldmatrix.sync.aligned.m8n8.x2.shared.b16 {%0,%1}, [%2];"
                 : "=r"(r[0]), "=r"(r[1]) : "r"(a));
}
__device__ __forceinline__ void ldmx2t(uint32_t (&r)[2], uint32_t a) {
    asm volatile("ldmatrix.sync.aligned.m8n8.x2.trans.shared.b16 {%0,%1}, [%2];"
                 : "=r"(r[0]), "=r"(r[1]) : "r"(a));
}
__device__ __forceinline__ void mma16816(float (&d)[4], const uint32_t (&A)[4],
                                         uint32_t b0, uint32_t b1) {
    asm volatile("mma.sync.aligned.m16n8k16.row.col.f32.bf16.bf16.f32 "
                 "{%0,%1,%2,%3},{%4,%5,%6,%7},{%8,%9},{%0,%1,%2,%3};"
                 : "+f"(d[0]), "+f"(d[1]), "+f"(d[2]), "+f"(d[3])
                 : "r"(A[0]), "r"(A[1]), "r"(A[2]), "r"(A[3]), "r"(b0), "r"(b1));
}
__device__ __forceinline__ uint32_t packbf(float lo, float hi) {
    __nv_bfloat162 t = __floats2bfloat162_rn(lo, hi);
    return *reinterpret_cast<uint32_t*>(&t);
}

// fp32 -> bf16 weight conversion (once per launch; cheap)
__global__ void conv_kernel(const float* __restrict__ a, const float* __restrict__ b,
                            const float* __restrict__ c, const float* __restrict__ d) {
    int i = blockIdx.x * 256 + threadIdx.x;     // 768 blocks -> 196608
    if (i < 49152)        g_wqkv[i]          = __float2bfloat16_rn(a[i]);
    else if (i < 65536)   g_wproj[i - 49152] = __float2bfloat16_rn(b[i - 49152]);
    else if (i < 131072)  g_wfc1[i - 65536]  = __float2bfloat16_rn(c[i - 65536]);
    else                  g_wfc2[i - 131072] = __float2bfloat16_rn(d[i - 131072]);
}

// ============================================================================
// Kernel 1: shift + partition + LN1 + QKV + masked attn + proj + residual.
// 1 block = 1 window (64 tokens), 256 threads = 8 warps.
// ============================================================================
#define S1 136
#define SM1_BYTES (5 * 64 * 136 * 2)

__global__ __launch_bounds__(256)
void attn_kernel(const float* __restrict__ x,
                 const float* __restrict__ qkv_b,
                 const float* __restrict__ proj_b,
                 const float* __restrict__ ln1_s,
                 const float* __restrict__ ln1_b,
                 float* __restrict__ out)
{
    extern __shared__ char smem[];
    __nv_bfloat16* XN = (__nv_bfloat16*)smem;
    __nv_bfloat16* QS = XN + 64 * S1;
    __nv_bfloat16* KS = QS + 64 * S1;
    __nv_bfloat16* VS = KS + 64 * S1;
    __nv_bfloat16* AO = VS + 64 * S1;
    float* OUTS = (float*)smem;   // f32 [64][132], aliases XN+QS (dead by Phase D write)

    const int tid  = threadIdx.x;
    const int lane = tid & 31;
    const int warp = tid >> 5;
    const int n  = blockIdx.x;
    const int wi = n & (NWIN - 1);
    const int fi = (n >> 2) & (FFI - 1);
    const int b  = n >> 9;

    const int r  = lane >> 2;          // 0..7
    const int c2 = (lane & 3) * 2;     // 0,2,4,6
    const int arow  = lane & 15;
    const int acol8 = (lane >> 4) * 8;

    // Phase A: gather (roll -2 along frames) + LN1 -> XN (bf16)
    {
        const int l = tid >> 2;
        const int q = tid & 3;
        const int tp = l >> 4, w16 = l & 15;
        int srcf = fi * 4 + tp + 2;
        if (srcf >= FDIM) srcf -= FDIM;
        const int kk = wi * 16 + w16;
        const float* xp = x + (((size_t)b * FDIM + srcf) * KDIM + kk) * EDIM + q * 32;
        float v[32];
#pragma unroll
        for (int i = 0; i < 8; i++) {
            float4 t = reinterpret_cast<const float4*>(xp)[i];
            v[4*i] = t.x; v[4*i+1] = t.y; v[4*i+2] = t.z; v[4*i+3] = t.w;
        }
        float s1 = 0.f, s2 = 0.f;
#pragma unroll
        for (int i = 0; i < 32; i++) { s1 += v[i]; s2 += v[i] * v[i]; }
        s1 += __shfl_xor_sync(0xffffffffu, s1, 1);
        s2 += __shfl_xor_sync(0xffffffffu, s2, 1);
        s1 += __shfl_xor_sync(0xffffffffu, s1, 2);
        s2 += __shfl_xor_sync(0xffffffffu, s2, 2);
        const float mean = s1 * (1.f / 128.f);
        const float rstd = rsqrtf(s2 * (1.f / 128.f) - mean * mean + LN_EPS);
#pragma unroll
        for (int i = 0; i < 16; i++) {
            const int c = q * 32 + 2 * i;
            float a0 = (v[2*i]   - mean) * rstd * ln1_s[c]     + ln1_b[c];
            float a1 = (v[2*i+1] - mean) * rstd * ln1_s[c + 1] + ln1_b[c + 1];
            *(uint32_t*)&XN[l * S1 + c] = packbf(a0, a1);
        }
    }
    __syncthreads();

    // Phase B: QKV GEMM, 3 passes of N=128, each warp owns a 16-wide n slice
    {
        const int nrow0 = warp * 16;
#pragma unroll
        for (int p = 0; p < 3; p++) {
            float acc[4][2][4];
#pragma unroll
            for (int mt = 0; mt < 4; mt++)
#pragma unroll
                for (int j = 0; j < 2; j++)
#pragma unroll
                    for (int e = 0; e < 4; e++) acc[mt][j][e] = 0.f;
            const __nv_bfloat16* Wg = g_wqkv + (size_t)(p * 128 + nrow0) * 128;
#pragma unroll
            for (int kt = 0; kt < 8; kt++) {
                uint32_t B0[2], B1[2];
#pragma unroll
                for (int j = 0; j < 2; j++) {
                    const __nv_bfloat16* bp = Wg + (j * 8 + r) * 128 + kt * 16 + c2;
                    B0[j] = *reinterpret_cast<const uint32_t*>(bp);
                    B1[j] = *reinterpret_cast<const uint32_t*>(bp + 8);
                }
#pragma unroll
                for (int mt = 0; mt < 4; mt++) {
                    uint32_t A[4];
                    ldmx4(A, sa(&XN[(mt * 16 + arow) * S1 + kt * 16 + acol8]));
                    mma16816(acc[mt][0], A, B0[0], B1[0]);
                    mma16816(acc[mt][1], A, B0[1], B1[1]);
                }
            }
            __nv_bfloat16* dst = (p == 0) ? QS : (p == 1) ? KS : VS;
#pragma unroll
            for (int mt = 0; mt < 4; mt++)
#pragma unroll
                for (int j = 0; j < 2; j++) {
                    const int col = nrow0 + j * 8 + c2;
                    const float b0v = qkv_b[p * 128 + col];
                    const float b1v = qkv_b[p * 128 + col + 1];
                    float v00 = acc[mt][j][0] + b0v, v01 = acc[mt][j][1] + b1v;
                    float v10 = acc[mt][j][2] + b0v, v11 = acc[mt][j][3] + b1v;
                    if (p == 0) { v00 *= QK_SCALE; v01 *= QK_SCALE; v10 *= QK_SCALE; v11 *= QK_SCALE; }
                    *(uint32_t*)&dst[(mt * 16 + r) * S1 + col]     = packbf(v00, v01);
                    *(uint32_t*)&dst[(mt * 16 + r + 8) * S1 + col] = packbf(v10, v11);
                }
        }
    }
    __syncthreads();

    // Phase C: scores + mask + softmax + PV, all in fragments.
    // warp h = warp>>1, m-half = (warp&1)*32
    {
        const int h  = warp >> 1;
        const int m0 = (warp & 1) * 32;
        const bool maskwin = (fi == FFI - 1);

        uint32_t qa[2][2][4];
#pragma unroll
        for (int mt = 0; mt < 2; mt++)
#pragma unroll
            for (int kt = 0; kt < 2; kt++)
                ldmx4(qa[mt][kt], sa(&QS[(m0 + mt * 16 + arow) * S1 + h * 32 + kt * 16 + acol8]));

        float s[2][8][4];
#pragma unroll
        for (int mt = 0; mt < 2; mt++)
#pragma unroll
            for (int j = 0; j < 8; j++)
#pragma unroll
                for (int e = 0; e < 4; e++) s[mt][j][e] = 0.f;

#pragma unroll
        for (int j = 0; j < 8; j++)
#pragma unroll
            for (int kt = 0; kt < 2; kt++) {
                uint32_t kb[2];
                ldmx2(kb, sa(&KS[(j * 8 + (lane & 7)) * S1 + h * 32 + kt * 16 + ((lane >> 3) & 1) * 8]));
                mma16816(s[0][j], qa[0][kt], kb[0], kb[1]);
                mma16816(s[1][j], qa[1][kt], kb[0], kb[1]);
            }

        // mask + softmax; C-frag row a = m+r, row b = m+r+8; n8 tile j is
        // fully inside one 32-column half (j<4 left half, j>=4 right half)
#pragma unroll
        for (int mt = 0; mt < 2; mt++) {
            const int ra = m0 + mt * 16 + r;
            const int rb = ra + 8;
            const bool qah = (ra < 32), qbh = (rb < 32);
            float mxa = -1e30f, mxb = -1e30f;
#pragma unroll
            for (int j = 0; j < 8; j++) {
                const bool cq = (j < 4);
                float* v = s[mt][j];
                if (maskwin && (qah != cq)) { v[0] = -10000.f; v[1] = -10000.f; }
                else { if (v[0] == 0.f) v[0] = -10000.f; if (v[1] == 0.f) v[1] = -10000.f; }
                if (maskwin && (qbh != cq)) { v[2] = -10000.f; v[3] = -10000.f; }
                else { if (v[2] == 0.f) v[2] = -10000.f; if (v[3] == 0.f) v[3] = -10000.f; }
                mxa = fmaxf(mxa, fmaxf(v[0], v[1]));
                mxb = fmaxf(mxb, fmaxf(v[2], v[3]));
            }
            mxa = fmaxf(mxa, __shfl_xor_sync(0xffffffffu, mxa, 1));
            mxa = fmaxf(mxa, __shfl_xor_sync(0xffffffffu, mxa, 2));
            mxb = fmaxf(mxb, __shfl_xor_sync(0xffffffffu, mxb, 1));
            mxb = fmaxf(mxb, __shfl_xor_sync(0xffffffffu, mxb, 2));
            float sma = 0.f, smb = 0.f;
#pragma unroll
            for (int j = 0; j < 8; j++) {
                float* v = s[mt][j];
                v[0] = __expf(v[0] - mxa); v[1] = __expf(v[1] - mxa);
                v[2] = __expf(v[2] - mxb); v[3] = __expf(v[3] - mxb);
                sma += v[0] + v[1]; smb += v[2] + v[3];
            }
            sma += __shfl_xor_sync(0xffffffffu, sma, 1);
            sma += __shfl_xor_sync(0xffffffffu, sma, 2);
            smb += __shfl_xor_sync(0xffffffffu, smb, 1);
            smb += __shfl_xor_sync(0xffffffffu, smb, 2);
            const float ia = 1.f / sma, ib = 1.f / smb;
#pragma unroll
            for (int j = 0; j < 8; j++) {
                float* v = s[mt][j];
                v[0] *= ia; v[1] *= ia; v[2] *= ib; v[3] *= ib;
            }
        }

        // PV: C-frag of scores repacks exactly into A-frag layout for k16 tiles
        float o[2][4][4];
#pragma unroll
        for (int mt = 0; mt < 2; mt++)
#pragma unroll
            for (int j2 = 0; j2 < 4; j2++)
#pragma unroll
                for (int e = 0; e < 4; e++) o[mt][j2][e] = 0.f;
#pragma unroll
        for (int kt = 0; kt < 4; kt++) {
            uint32_t pa[2][4];
#pragma unroll
            for (int mt = 0; mt < 2; mt++) {
                pa[mt][0] = packbf(s[mt][2*kt][0],   s[mt][2*kt][1]);
                pa[mt][1] = packbf(s[mt][2*kt][2],   s[mt][2*kt][3]);
                pa[mt][2] = packbf(s[mt][2*kt+1][0], s[mt][2*kt+1][1]);
                pa[mt][3] = packbf(s[mt][2*kt+1][2], s[mt][2*kt+1][3]);
            }
#pragma unroll
            for (int j2 = 0; j2 < 4; j2++) {
                uint32_t vb[2];
                ldmx2t(vb, sa(&VS[(kt * 16 + arow) * S1 + h * 32 + j2 * 8]));
                mma16816(o[0][j2], pa[0], vb[0], vb[1]);
                mma16816(o[1][j2], pa[1], vb[0], vb[1]);
            }
        }
#pragma unroll
        for (int mt = 0; mt < 2; mt++)
#pragma unroll
            for (int j2 = 0; j2 < 4; j2++) {
                const int row = m0 + mt * 16 + r;
                const int col = h * 32 + j2 * 8 + c2;
                *(uint32_t*)&AO[row * S1 + col]       = packbf(o[mt][j2][0], o[mt][j2][1]);
                *(uint32_t*)&AO[(row + 8) * S1 + col] = packbf(o[mt][j2][2], o[mt][j2][3]);
            }
    }
    __syncthreads();

    // Phase D: proj (64x128x128) -> OUTS fp32
    {
        const int nrow0 = warp * 16;
        float acc[4][2][4];
#pragma unroll
        for (int mt = 0; mt < 4; mt++)
#pragma unroll
            for (int j = 0; j < 2; j++)
#pragma unroll
                for (int e = 0; e < 4; e++) acc[mt][j][e] = 0.f;
        const __nv_bfloat16* Wg = g_wproj + (size_t)nrow0 * 128;
#pragma unroll
        for (int kt = 0; kt < 8; kt++) {
            uint32_t B0[2], B1[2];
#pragma unroll
            for (int j = 0; j < 2; j++) {
                const __nv_bfloat16* bp = Wg + (j * 8 + r) * 128 + kt * 16 + c2;
                B0[j] = *reinterpret_cast<const uint32_t*>(bp);
                B1[j] = *reinterpret_cast<const uint32_t*>(bp + 8);
            }
#pragma unroll
            for (int mt = 0; mt < 4; mt++) {
                uint32_t A[4];
                ldmx4(A, sa(&AO[(mt * 16 + arow) * S1 + kt * 16 + acol8]));
                mma16816(acc[mt][0], A, B0[0], B1[0]);
                mma16816(acc[mt][1], A, B0[1], B1[1]);
            }
        }
        __syncthreads();   // OUTS aliases XN/QS region; order writes after all reads
#pragma unroll
        for (int mt = 0; mt < 4; mt++)
#pragma unroll
            for (int j = 0; j < 2; j++) {
                const int col = nrow0 + j * 8 + c2;
                const float b0v = proj_b[col], b1v = proj_b[col + 1];
                *(float2*)&OUTS[(mt * 16 + r) * 132 + col] =
                    make_float2(acc[mt][j][0] + b0v, acc[mt][j][1] + b1v);
                *(float2*)&OUTS[(mt * 16 + r + 8) * 132 + col] =
                    make_float2(acc[mt][j][2] + b0v, acc[mt][j][3] + b1v);
            }
    }
    __syncthreads();

    // Phase E: roll(+2 along window tokens) + window reverse + residual
    {
        const int lp = tid >> 2;
        const int q  = tid & 3;
        const int tp = lp >> 4, w16 = lp & 15;
        const int lsrc = (lp - 2 + LWIN) & (LWIN - 1);
        const int frame = fi * 4 + tp;
        const int kk = wi * 16 + w16;
        const size_t base = (((size_t)b * FDIM + frame) * KDIM + kk) * EDIM + q * 32;
        const float* xp = x + base;
        float* op = out + base;
#pragma unroll
        for (int i = 0; i < 8; i++) {
            float4 t = reinterpret_cast<const float4*>(xp)[i];
            const int c = q * 32 + 4 * i;
            t.x += OUTS[lsrc * 132 + c];
            t.y += OUTS[lsrc * 132 + c + 1];
            t.z += OUTS[lsrc * 132 + c + 2];
            t.w += OUTS[lsrc * 132 + c + 3];
            reinterpret_cast<float4*>(op)[i] = t;
        }
    }
}

// ============================================================================
// Kernel 2: LN2 + fc1 + GELU + fc2 + residual. 128 tokens/block, 8 warps.
// ============================================================================
#define S2 136
#define A1S 72
#define SM2_BYTES (128 * 132 * 4)

__global__ __launch_bounds__(256)
void mlp_kernel(float* __restrict__ io,
                const float* __restrict__ ln2_s,
                const float* __restrict__ ln2_b,
                const float* __restrict__ fc1_b,
                const float* __restrict__ fc2_b)
{
    extern __shared__ char smem[];
    __nv_bfloat16* XS = (__nv_bfloat16*)smem;            // [128][136] bf16
    __nv_bfloat16* A1 = (__nv_bfloat16*)(smem + 34816);  // [128][72] bf16
    float* HS = (float*)smem;                            // [128][132] f32 alias

    const int tid  = threadIdx.x;
    const int lane = tid & 31;
    const int warp = tid >> 5;
    const size_t tok0 = (size_t)blockIdx.x * 128;

    const int r  = lane >> 2;
    const int c2 = (lane & 3) * 2;
    const int arow  = lane & 15;
    const int acol8 = (lane >> 4) * 8;

    // LN2 -> XS bf16
    {
        const int l = tid >> 1;
        const int q = tid & 1;
        const float* xp = io + (tok0 + l) * EDIM + q * 64;
        float v[64];
#pragma unroll
        for (int i = 0; i < 16; i++) {
            float4 t = reinterpret_cast<const float4*>(xp)[i];
            v[4*i] = t.x; v[4*i+1] = t.y; v[4*i+2] = t.z; v[4*i+3] = t.w;
        }
        float s1 = 0.f, s2 = 0.f;
#pragma unroll
        for (int i = 0; i < 64; i++) { s1 += v[i]; s2 += v[i] * v[i]; }
        s1 += __shfl_xor_sync(0xffffffffu, s1, 1);
        s2 += __shfl_xor_sync(0xffffffffu, s2, 1);
        const float mean = s1 * (1.f / 128.f);
        const float rstd = rsqrtf(s2 * (1.f / 128.f) - mean * mean + LN_EPS);
#pragma unroll
        for (int i = 0; i < 32; i++) {
            const int c = q * 64 + 2 * i;
            float a0 = (v[2*i]   - mean) * rstd * ln2_s[c]     + ln2_b[c];
            float a1 = (v[2*i+1] - mean) * rstd * ln2_s[c + 1] + ln2_b[c + 1];
            *(uint32_t*)&XS[l * S2 + c] = packbf(a0, a1);
        }
    }
    __syncthreads();

    // fc1 / GELU / fc2 streamed over 8 chunks of 64 hidden units
    float hacc[8][2][4];
#pragma unroll
    for (int mt = 0; mt < 8; mt++)
#pragma unroll
        for (int j = 0; j < 2; j++)
#pragma unroll
            for (int e = 0; e < 4; e++) hacc[mt][j][e] = 0.f;

    const int col0 = warp * 16;   // fc2 output slice owned by this warp

    for (int nc = 0; nc < 8; nc++) {
        // fc1: warp computes its n8 slice for all 128 tokens
        float c1[8][4];
#pragma unroll
        for (int mt = 0; mt < 8; mt++)
#pragma unroll
            for (int e = 0; e < 4; e++) c1[mt][e] = 0.f;
        const __nv_bfloat16* Wg1 = g_wfc1 + (size_t)(nc * 64 + warp * 8) * 128;
#pragma unroll
        for (int kt = 0; kt < 8; kt++) {
            const __nv_bfloat16* bp = Wg1 + r * 128 + kt * 16 + c2;
            const uint32_t b0 = *reinterpret_cast<const uint32_t*>(bp);
            const uint32_t b1 = *reinterpret_cast<const uint32_t*>(bp + 8);
#pragma unroll
            for (int mt = 0; mt < 8; mt++) {
                uint32_t A[4];
                ldmx4(A, sa(&XS[(mt * 16 + arow) * S2 + kt * 16 + acol8]));
                mma16816(c1[mt], A, b0, b1);
            }
        }
        // GELU (exact erf) + store bf16 activation tile
#pragma unroll
        for (int mt = 0; mt < 8; mt++) {
            const int gn = nc * 64 + warp * 8 + c2;
            const float b0v = fc1_b[gn], b1v = fc1_b[gn + 1];
            float v0 = c1[mt][0] + b0v, v1 = c1[mt][1] + b1v;
            float v2 = c1[mt][2] + b0v, v3 = c1[mt][3] + b1v;
            v0 = 0.5f * v0 * (1.f + erff(v0 * 0.70710678118654752f));
            v1 = 0.5f * v1 * (1.f + erff(v1 * 0.70710678118654752f));
            v2 = 0.5f * v2 * (1.f + erff(v2 * 0.70710678118654752f));
            v3 = 0.5f * v3 * (1.f + erff(v3 * 0.70710678118654752f));
            const int lc = warp * 8 + c2;
            *(uint32_t*)&A1[(mt * 16 + r) * A1S + lc]     = packbf(v0, v1);
            *(uint32_t*)&A1[(mt * 16 + r + 8) * A1S + lc] = packbf(v2, v3);
        }
        __syncthreads();

        // fc2 partial accumulate into registers
        const __nv_bfloat16* Wg2 = g_wfc2 + (size_t)col0 * 512 + nc * 64;
#pragma unroll
        for (int kt = 0; kt < 4; kt++) {
            uint32_t B0[2], B1[2];
#pragma unroll
            for (int j = 0; j < 2; j++) {
                const __nv_bfloat16* bp = Wg2 + (size_t)(j * 8 + r) * 512 + kt * 16 + c2;
                B0[j] = *reinterpret_cast<const uint32_t*>(bp);
                B1[j] = *reinterpret_cast<const uint32_t*>(bp + 8);
            }
#pragma unroll
            for (int mt = 0; mt < 8; mt++) {
                uint32_t A[4];
                ldmx4(A, sa(&A1[(mt * 16 + arow) * A1S + kt * 16 + acol8]));
                mma16816(hacc[mt][0], A, B0[0], B1[0]);
                mma16816(hacc[mt][1], A, B0[1], B1[1]);
            }
        }
        __syncthreads();
    }

    // stage h (+fc2 bias) into HS then coalesced residual add
#pragma unroll
    for (int mt = 0; mt < 8; mt++)
#pragma unroll
        for (int j = 0; j < 2; j++) {
            const int col = col0 + j * 8 + c2;
            const float b0v = fc2_b[col], b1v = fc2_b[col + 1];
            *(float2*)&HS[(mt * 16 + r) * 132 + col] =
                make_float2(hacc[mt][j][0] + b0v, hacc[mt][j][1] + b1v);
            *(float2*)&HS[(mt * 16 + r + 8) * 132 + col] =
                make_float2(hacc[mt][j][2] + b0v, hacc[mt][j][3] + b1v);
        }
    __syncthreads();
    {
        const int l = tid >> 1;
        const int q = tid & 1;
        float* iop = io + (tok0 + l) * EDIM + q * 64;
#pragma unroll
        for (int i = 0; i < 16; i++) {
            float4 t = reinterpret_cast<const float4*>(iop)[i];
            const int c = q * 64 + 4 * i;
            t.x += HS[l * 132 + c];
            t.y += HS[l * 132 + c + 1];
            t.z += HS[l * 132 + c + 2];
            t.w += HS[l * 132 + c + 3];
            reinterpret_cast<float4*>(iop)[i] = t;
        }
    }
}

extern "C" void kernel_launch(void* const* d_in, const int* in_sizes, int n_in,
                              void* d_out, int out_size)
{
    const float* x      = (const float*)d_in[0];
    const float* qkv_w  = (const float*)d_in[1];
    const float* qkv_b  = (const float*)d_in[2];
    const float* proj_w = (const float*)d_in[3];
    const float* proj_b = (const float*)d_in[4];
    const float* ln1_s  = (const float*)d_in[5];
    const float* ln1_b  = (const float*)d_in[6];
    const float* ln2_s  = (const float*)d_in[7];
    const float* ln2_b  = (const float*)d_in[8];
    const float* fc1_w  = (const float*)d_in[9];
    const float* fc1_b  = (const float*)d_in[10];
    const float* fc2_w  = (const float*)d_in[11];
    const float* fc2_b  = (const float*)d_in[12];
    float* out = (float*)d_out;

    cudaFuncSetAttribute(attn_kernel, cudaFuncAttributeMaxDynamicSharedMemorySize, SM1_BYTES);
    cudaFuncSetAttribute(mlp_kernel,  cudaFuncAttributeMaxDynamicSharedMemorySize, SM2_BYTES);

    conv_kernel<<<768, 256>>>(qkv_w, proj_w, fc1_w, fc2_w);
    attn_kernel<<<4096, 256, SM1_BYTES>>>(x, qkv_b, proj_b, ln1_s, ln1_b, out);
    mlp_kernel<<<2048, 256, SM2_BYTES>>>(out, ln2_s, ln2_b, fc1_b, fc2_b);
}

// round 6
// speedup vs baseline: 4.5710x; 1.1265x over previous
#include <cuda_runtime.h>
#include <cuda_bf16.h>
#include <math.h>
#include <stdint.h>

#define BATCH  8
#define FDIM   512
#define KDIM   64
#define EDIM   128
#define NHEAD  4
#define LWIN   64
#define FFI    128
#define NWIN   4
#define QK_SCALE 0.17677669529663687f
#define LN_EPS 1e-5f

__device__ __nv_bfloat16 g_wqkv[384 * 128];
__device__ __nv_bfloat16 g_wproj[128 * 128];
// fragment-packed fc weights: one uint4 = {b0(kt even), b1(kt even), b0(kt odd), b1(kt odd)}
__device__ uint4 g_wfc1p[8192];   // 512x128 bf16, packed
__device__ uint4 g_wfc2p[8192];   // 128x512 bf16, packed

__device__ __forceinline__ uint32_t sa(const void* p) {
    return (uint32_t)__cvta_generic_to_shared(p);
}
__device__ __forceinline__ void ldmx4(uint32_t (&r)[4], uint32_t a) {
    asm volatile("ldmatrix.sync.aligned.m8n8.x4.shared.b16 {%0,%1,%2,%3}, [%4];"
                 : "=r"(r[0]), "=r"(r[1]), "=r"(r[2]), "=r"(r[3]) : "r"(a));
}
__device__ __forceinline__ void ldmx2(uint32_t (&r)[2], uint32_t a) {
    asm volatile("ldmatrix.sync.aligned.m8n8.x2.shared.b16 {%0,%1}, [%2];"
                 : "=r"(r[0]), "=r"(r[1]) : "r"(a));
}
__device__ __forceinline__ void ldmx2t(uint32_t (&r)[2], uint32_t a) {
    asm volatile("ldmatrix.sync.aligned.m8n8.x2.trans.shared.b16 {%0,%1}, [%2];"
                 : "=r"(r[0]), "=r"(r[1]) : "r"(a));
}
__device__ __forceinline__ void mma16816(float (&d)[4], const uint32_t (&A)[4],
                                         uint32_t b0, uint32_t b1) {
    asm volatile("mma.sync.aligned.m16n8k16.row.col.f32.bf16.bf16.f32 "
                 "{%0,%1,%2,%3},{%4,%5,%6,%7},{%8,%9},{%0,%1,%2,%3};"
                 : "+f"(d[0]), "+f"(d[1]), "+f"(d[2]), "+f"(d[3])
                 : "r"(A[0]), "r"(A[1]), "r"(A[2]), "r"(A[3]), "r"(b0), "r"(b1));
}
__device__ __forceinline__ uint32_t packbf(float lo, float hi) {
    __nv_bfloat162 t = __floats2bfloat162_rn(lo, hi);
    return *reinterpret_cast<uint32_t*>(&t);
}

// ---- weight conversion kernels (cheap, once per launch) ----
__global__ void conv_attn(const float* __restrict__ a, const float* __restrict__ b) {
    int i = blockIdx.x * 256 + threadIdx.x;   // 256 blocks -> 65536
    if (i < 49152) g_wqkv[i] = __float2bfloat16_rn(a[i]);
    else           g_wproj[i - 49152] = __float2bfloat16_rn(b[i - 49152]);
}
// pack fc1 (512x128): jg in [0,64), u in [0,4) pairs of k16 tiles, lane, e in [0,4)
__global__ void conv_fc1p(const float* __restrict__ w) {
    int tid = blockIdx.x * 256 + threadIdx.x;    // 128 blocks -> 32768 u32 outputs
    int e = tid & 3, lane = (tid >> 2) & 31, u = (tid >> 7) & 3, jg = tid >> 9;
    int r = lane >> 2, c2 = (lane & 3) * 2;
    int row = jg * 8 + r;
    int cb = 32 * u + (e >> 1) * 16 + (e & 1) * 8 + c2;
    __nv_bfloat16* dst = (__nv_bfloat16*)g_wfc1p;
    dst[tid * 2]     = __float2bfloat16_rn(w[row * 128 + cb]);
    dst[tid * 2 + 1] = __float2bfloat16_rn(w[row * 128 + cb + 1]);
}
// pack fc2 (128x512): jg in [0,16), u in [0,16) pairs of k16 tiles
__global__ void conv_fc2p(const float* __restrict__ w) {
    int tid = blockIdx.x * 256 + threadIdx.x;    // 128 blocks -> 32768
    int e = tid & 3, lane = (tid >> 2) & 31, u = (tid >> 7) & 15, jg = tid >> 11;
    int r = lane >> 2, c2 = (lane & 3) * 2;
    int row = jg * 8 + r;
    int cb = 32 * u + (e >> 1) * 16 + (e & 1) * 8 + c2;
    __nv_bfloat16* dst = (__nv_bfloat16*)g_wfc2p;
    dst[tid * 2]     = __float2bfloat16_rn(w[row * 512 + cb]);
    dst[tid * 2 + 1] = __float2bfloat16_rn(w[row * 512 + cb + 1]);
}

// ============================================================================
// Kernel 1: shift + partition + LN1 + QKV + masked attn + proj + residual.
// 1 block = 1 window (64 tokens), 256 threads = 8 warps.  (UNCHANGED, verified)
// ============================================================================
#define S1 136
#define SM1_BYTES (5 * 64 * 136 * 2)

__global__ __launch_bounds__(256)
void attn_kernel(const float* __restrict__ x,
                 const float* __restrict__ qkv_b,
                 const float* __restrict__ proj_b,
                 const float* __restrict__ ln1_s,
                 const float* __restrict__ ln1_b,
                 float* __restrict__ out)
{
    extern __shared__ char smem[];
    __nv_bfloat16* XN = (__nv_bfloat16*)smem;
    __nv_bfloat16* QS = XN + 64 * S1;
    __nv_bfloat16* KS = QS + 64 * S1;
    __nv_bfloat16* VS = KS + 64 * S1;
    __nv_bfloat16* AO = VS + 64 * S1;
    float* OUTS = (float*)smem;

    const int tid  = threadIdx.x;
    const int lane = tid & 31;
    const int warp = tid >> 5;
    const int n  = blockIdx.x;
    const int wi = n & (NWIN - 1);
    const int fi = (n >> 2) & (FFI - 1);
    const int b  = n >> 9;

    const int r  = lane >> 2;
    const int c2 = (lane & 3) * 2;
    const int arow  = lane & 15;
    const int acol8 = (lane >> 4) * 8;

    // Phase A: gather (roll -2 along frames) + LN1 -> XN (bf16)
    {
        const int l = tid >> 2;
        const int q = tid & 3;
        const int tp = l >> 4, w16 = l & 15;
        int srcf = fi * 4 + tp + 2;
        if (srcf >= FDIM) srcf -= FDIM;
        const int kk = wi * 16 + w16;
        const float* xp = x + (((size_t)b * FDIM + srcf) * KDIM + kk) * EDIM + q * 32;
        float v[32];
#pragma unroll
        for (int i = 0; i < 8; i++) {
            float4 t = reinterpret_cast<const float4*>(xp)[i];
            v[4*i] = t.x; v[4*i+1] = t.y; v[4*i+2] = t.z; v[4*i+3] = t.w;
        }
        float s1 = 0.f, s2 = 0.f;
#pragma unroll
        for (int i = 0; i < 32; i++) { s1 += v[i]; s2 += v[i] * v[i]; }
        s1 += __shfl_xor_sync(0xffffffffu, s1, 1);
        s2 += __shfl_xor_sync(0xffffffffu, s2, 1);
        s1 += __shfl_xor_sync(0xffffffffu, s1, 2);
        s2 += __shfl_xor_sync(0xffffffffu, s2, 2);
        const float mean = s1 * (1.f / 128.f);
        const float rstd = rsqrtf(s2 * (1.f / 128.f) - mean * mean + LN_EPS);
#pragma unroll
        for (int i = 0; i < 16; i++) {
            const int c = q * 32 + 2 * i;
            float a0 = (v[2*i]   - mean) * rstd * ln1_s[c]     + ln1_b[c];
            float a1 = (v[2*i+1] - mean) * rstd * ln1_s[c + 1] + ln1_b[c + 1];
            *(uint32_t*)&XN[l * S1 + c] = packbf(a0, a1);
        }
    }
    __syncthreads();

    // Phase B: QKV GEMM, 3 passes of N=128, each warp owns a 16-wide n slice
    {
        const int nrow0 = warp * 16;
#pragma unroll
        for (int p = 0; p < 3; p++) {
            float acc[4][2][4];
#pragma unroll
            for (int mt = 0; mt < 4; mt++)
#pragma unroll
                for (int j = 0; j < 2; j++)
#pragma unroll
                    for (int e = 0; e < 4; e++) acc[mt][j][e] = 0.f;
            const __nv_bfloat16* Wg = g_wqkv + (size_t)(p * 128 + nrow0) * 128;
#pragma unroll
            for (int kt = 0; kt < 8; kt++) {
                uint32_t B0[2], B1[2];
#pragma unroll
                for (int j = 0; j < 2; j++) {
                    const __nv_bfloat16* bp = Wg + (j * 8 + r) * 128 + kt * 16 + c2;
                    B0[j] = *reinterpret_cast<const uint32_t*>(bp);
                    B1[j] = *reinterpret_cast<const uint32_t*>(bp + 8);
                }
#pragma unroll
                for (int mt = 0; mt < 4; mt++) {
                    uint32_t A[4];
                    ldmx4(A, sa(&XN[(mt * 16 + arow) * S1 + kt * 16 + acol8]));
                    mma16816(acc[mt][0], A, B0[0], B1[0]);
                    mma16816(acc[mt][1], A, B0[1], B1[1]);
                }
            }
            __nv_bfloat16* dst = (p == 0) ? QS : (p == 1) ? KS : VS;
#pragma unroll
            for (int mt = 0; mt < 4; mt++)
#pragma unroll
                for (int j = 0; j < 2; j++) {
                    const int col = nrow0 + j * 8 + c2;
                    const float b0v = qkv_b[p * 128 + col];
                    const float b1v = qkv_b[p * 128 + col + 1];
                    float v00 = acc[mt][j][0] + b0v, v01 = acc[mt][j][1] + b1v;
                    float v10 = acc[mt][j][2] + b0v, v11 = acc[mt][j][3] + b1v;
                    if (p == 0) { v00 *= QK_SCALE; v01 *= QK_SCALE; v10 *= QK_SCALE; v11 *= QK_SCALE; }
                    *(uint32_t*)&dst[(mt * 16 + r) * S1 + col]     = packbf(v00, v01);
                    *(uint32_t*)&dst[(mt * 16 + r + 8) * S1 + col] = packbf(v10, v11);
                }
        }
    }
    __syncthreads();

    // Phase C: scores + mask + softmax + PV, all in fragments.
    {
        const int h  = warp >> 1;
        const int m0 = (warp & 1) * 32;
        const bool maskwin = (fi == FFI - 1);

        uint32_t qa[2][2][4];
#pragma unroll
        for (int mt = 0; mt < 2; mt++)
#pragma unroll
            for (int kt = 0; kt < 2; kt++)
                ldmx4(qa[mt][kt], sa(&QS[(m0 + mt * 16 + arow) * S1 + h * 32 + kt * 16 + acol8]));

        float s[2][8][4];
#pragma unroll
        for (int mt = 0; mt < 2; mt++)
#pragma unroll
            for (int j = 0; j < 8; j++)
#pragma unroll
                for (int e = 0; e < 4; e++) s[mt][j][e] = 0.f;

#pragma unroll
        for (int j = 0; j < 8; j++)
#pragma unroll
            for (int kt = 0; kt < 2; kt++) {
                uint32_t kb[2];
                ldmx2(kb, sa(&KS[(j * 8 + (lane & 7)) * S1 + h * 32 + kt * 16 + ((lane >> 3) & 1) * 8]));
                mma16816(s[0][j], qa[0][kt], kb[0], kb[1]);
                mma16816(s[1][j], qa[1][kt], kb[0], kb[1]);
            }

#pragma unroll
        for (int mt = 0; mt < 2; mt++) {
            const int ra = m0 + mt * 16 + r;
            const int rb = ra + 8;
            const bool qah = (ra < 32), qbh = (rb < 32);
            float mxa = -1e30f, mxb = -1e30f;
#pragma unroll
            for (int j = 0; j < 8; j++) {
                const bool cq = (j < 4);
                float* v = s[mt][j];
                if (maskwin && (qah != cq)) { v[0] = -10000.f; v[1] = -10000.f; }
                else { if (v[0] == 0.f) v[0] = -10000.f; if (v[1] == 0.f) v[1] = -10000.f; }
                if (maskwin && (qbh != cq)) { v[2] = -10000.f; v[3] = -10000.f; }
                else { if (v[2] == 0.f) v[2] = -10000.f; if (v[3] == 0.f) v[3] = -10000.f; }
                mxa = fmaxf(mxa, fmaxf(v[0], v[1]));
                mxb = fmaxf(mxb, fmaxf(v[2], v[3]));
            }
            mxa = fmaxf(mxa, __shfl_xor_sync(0xffffffffu, mxa, 1));
            mxa = fmaxf(mxa, __shfl_xor_sync(0xffffffffu, mxa, 2));
            mxb = fmaxf(mxb, __shfl_xor_sync(0xffffffffu, mxb, 1));
            mxb = fmaxf(mxb, __shfl_xor_sync(0xffffffffu, mxb, 2));
            float sma = 0.f, smb = 0.f;
#pragma unroll
            for (int j = 0; j < 8; j++) {
                float* v = s[mt][j];
                v[0] = __expf(v[0] - mxa); v[1] = __expf(v[1] - mxa);
                v[2] = __expf(v[2] - mxb); v[3] = __expf(v[3] - mxb);
                sma += v[0] + v[1]; smb += v[2] + v[3];
            }
            sma += __shfl_xor_sync(0xffffffffu, sma, 1);
            sma += __shfl_xor_sync(0xffffffffu, sma, 2);
            smb += __shfl_xor_sync(0xffffffffu, smb, 1);
            smb += __shfl_xor_sync(0xffffffffu, smb, 2);
            const float ia = 1.f / sma, ib = 1.f / smb;
#pragma unroll
            for (int j = 0; j < 8; j++) {
                float* v = s[mt][j];
                v[0] *= ia; v[1] *= ia; v[2] *= ib; v[3] *= ib;
            }
        }

        float o[2][4][4];
#pragma unroll
        for (int mt = 0; mt < 2; mt++)
#pragma unroll
            for (int j2 = 0; j2 < 4; j2++)
#pragma unroll
                for (int e = 0; e < 4; e++) o[mt][j2][e] = 0.f;
#pragma unroll
        for (int kt = 0; kt < 4; kt++) {
            uint32_t pa[2][4];
#pragma unroll
            for (int mt = 0; mt < 2; mt++) {
                pa[mt][0] = packbf(s[mt][2*kt][0],   s[mt][2*kt][1]);
                pa[mt][1] = packbf(s[mt][2*kt][2],   s[mt][2*kt][3]);
                pa[mt][2] = packbf(s[mt][2*kt+1][0], s[mt][2*kt+1][1]);
                pa[mt][3] = packbf(s[mt][2*kt+1][2], s[mt][2*kt+1][3]);
            }
#pragma unroll
            for (int j2 = 0; j2 < 4; j2++) {
                uint32_t vb[2];
                ldmx2t(vb, sa(&VS[(kt * 16 + arow) * S1 + h * 32 + j2 * 8]));
                mma16816(o[0][j2], pa[0], vb[0], vb[1]);
                mma16816(o[1][j2], pa[1], vb[0], vb[1]);
            }
        }
#pragma unroll
        for (int mt = 0; mt < 2; mt++)
#pragma unroll
            for (int j2 = 0; j2 < 4; j2++) {
                const int row = m0 + mt * 16 + r;
                const int col = h * 32 + j2 * 8 + c2;
                *(uint32_t*)&AO[row * S1 + col]       = packbf(o[mt][j2][0], o[mt][j2][1]);
                *(uint32_t*)&AO[(row + 8) * S1 + col] = packbf(o[mt][j2][2], o[mt][j2][3]);
            }
    }
    __syncthreads();

    // Phase D: proj (64x128x128) -> OUTS fp32
    {
        const int nrow0 = warp * 16;
        float acc[4][2][4];
#pragma unroll
        for (int mt = 0; mt < 4; mt++)
#pragma unroll
            for (int j = 0; j < 2; j++)
#pragma unroll
                for (int e = 0; e < 4; e++) acc[mt][j][e] = 0.f;
        const __nv_bfloat16* Wg = g_wproj + (size_t)nrow0 * 128;
#pragma unroll
        for (int kt = 0; kt < 8; kt++) {
            uint32_t B0[2], B1[2];
#pragma unroll
            for (int j = 0; j < 2; j++) {
                const __nv_bfloat16* bp = Wg + (j * 8 + r) * 128 + kt * 16 + c2;
                B0[j] = *reinterpret_cast<const uint32_t*>(bp);
                B1[j] = *reinterpret_cast<const uint32_t*>(bp + 8);
            }
#pragma unroll
            for (int mt = 0; mt < 4; mt++) {
                uint32_t A[4];
                ldmx4(A, sa(&AO[(mt * 16 + arow) * S1 + kt * 16 + acol8]));
                mma16816(acc[mt][0], A, B0[0], B1[0]);
                mma16816(acc[mt][1], A, B0[1], B1[1]);
            }
        }
        __syncthreads();
#pragma unroll
        for (int mt = 0; mt < 4; mt++)
#pragma unroll
            for (int j = 0; j < 2; j++) {
                const int col = nrow0 + j * 8 + c2;
                const float b0v = proj_b[col], b1v = proj_b[col + 1];
                *(float2*)&OUTS[(mt * 16 + r) * 132 + col] =
                    make_float2(acc[mt][j][0] + b0v, acc[mt][j][1] + b1v);
                *(float2*)&OUTS[(mt * 16 + r + 8) * 132 + col] =
                    make_float2(acc[mt][j][2] + b0v, acc[mt][j][3] + b1v);
            }
    }
    __syncthreads();

    // Phase E: roll(+2 along window tokens) + window reverse + residual
    {
        const int lp = tid >> 2;
        const int q  = tid & 3;
        const int tp = lp >> 4, w16 = lp & 15;
        const int lsrc = (lp - 2 + LWIN) & (LWIN - 1);
        const int frame = fi * 4 + tp;
        const int kk = wi * 16 + w16;
        const size_t base = (((size_t)b * FDIM + frame) * KDIM + kk) * EDIM + q * 32;
        const float* xp = x + base;
        float* op = out + base;
#pragma unroll
        for (int i = 0; i < 8; i++) {
            float4 t = reinterpret_cast<const float4*>(xp)[i];
            const int c = q * 32 + 4 * i;
            t.x += OUTS[lsrc * 132 + c];
            t.y += OUTS[lsrc * 132 + c + 1];
            t.z += OUTS[lsrc * 132 + c + 2];
            t.w += OUTS[lsrc * 132 + c + 3];
            reinterpret_cast<float4*>(op)[i] = t;
        }
    }
}

// ============================================================================
// Kernel 2 (REWORKED): LN2 + fc1 + GELU + fc2 + residual.
// 128 tokens/block, 8 warps; each warp owns 16 tokens end-to-end.
// A and activations register-resident; packed uint4 weight fragments from L1.
// No block-wide syncs.
// ============================================================================
#define S2 136
#define SM2_BYTES (128 * 136 * 2)

__global__ __launch_bounds__(256)
void mlp_kernel(float* __restrict__ io,
                const float* __restrict__ ln2_s,
                const float* __restrict__ ln2_b,
                const float* __restrict__ fc1_b,
                const float* __restrict__ fc2_b)
{
    extern __shared__ char smem[];
    __nv_bfloat16* XS = (__nv_bfloat16*)smem;   // [128][S2] bf16, warp-local slices

    const int tid  = threadIdx.x;
    const int lane = tid & 31;
    const int warp = tid >> 5;
    const size_t tok0 = (size_t)blockIdx.x * 128;

    const int r  = lane >> 2;
    const int c2 = (lane & 3) * 2;
    const int arow  = lane & 15;
    const int acol8 = (lane >> 4) * 8;

    // LN2 for this warp's 16 tokens (2 lanes per token) -> XS slice
    {
        const int l = warp * 16 + (lane >> 1);
        const int q = lane & 1;
        const float* xp = io + (tok0 + l) * EDIM + q * 64;
        float v[64];
#pragma unroll
        for (int i = 0; i < 16; i++) {
            float4 t = reinterpret_cast<const float4*>(xp)[i];
            v[4*i] = t.x; v[4*i+1] = t.y; v[4*i+2] = t.z; v[4*i+3] = t.w;
        }
        float s1 = 0.f, s2 = 0.f;
#pragma unroll
        for (int i = 0; i < 64; i++) { s1 += v[i]; s2 += v[i] * v[i]; }
        s1 += __shfl_xor_sync(0xffffffffu, s1, 1);
        s2 += __shfl_xor_sync(0xffffffffu, s2, 1);
        const float mean = s1 * (1.f / 128.f);
        const float rstd = rsqrtf(s2 * (1.f / 128.f) - mean * mean + LN_EPS);
#pragma unroll
        for (int i = 0; i < 32; i++) {
            const int c = q * 64 + 2 * i;
            float a0 = (v[2*i]   - mean) * rstd * ln2_s[c]     + ln2_b[c];
            float a1 = (v[2*i+1] - mean) * rstd * ln2_s[c + 1] + ln2_b[c + 1];
            *(uint32_t*)&XS[l * S2 + c] = packbf(a0, a1);
        }
    }
    __syncwarp();

    // Load A fragments once (16 tokens x 128 K), register-resident
    uint32_t a[8][4];
#pragma unroll
    for (int kt = 0; kt < 8; kt++)
        ldmx4(a[kt], sa(&XS[(warp * 16 + arow) * S2 + kt * 16 + acol8]));

    // fc2 accumulators: 16 tokens x 128 out, C-frag layout
    float hacc[16][4];
#pragma unroll
    for (int j2 = 0; j2 < 16; j2++)
#pragma unroll
        for (int e = 0; e < 4; e++) hacc[j2][e] = 0.f;

    for (int nc = 0; nc < 8; nc++) {
        // fc1: this warp's 16 tokens x 64 hidden units [nc*64, nc*64+64)
        float c1[8][4];
#pragma unroll
        for (int j = 0; j < 8; j++)
#pragma unroll
            for (int e = 0; e < 4; e++) c1[j][e] = 0.f;
#pragma unroll
        for (int u = 0; u < 4; u++)
#pragma unroll
            for (int j = 0; j < 8; j++) {
                const uint4 B = g_wfc1p[((nc * 8 + j) * 4 + u) * 32 + lane];
                mma16816(c1[j], a[2*u],     B.x, B.y);
                mma16816(c1[j], a[2*u + 1], B.z, B.w);
            }

        // bias + exact GELU + repack C-frag -> A-frag (registers only)
        uint32_t pa[4][4];
#pragma unroll
        for (int t = 0; t < 4; t++) {
            float g[2][4];
#pragma unroll
            for (int p = 0; p < 2; p++) {
                const int j = 2 * t + p;
                const int gn = nc * 64 + j * 8 + c2;
                const float b0v = fc1_b[gn], b1v = fc1_b[gn + 1];
                float v0 = c1[j][0] + b0v, v1 = c1[j][1] + b1v;
                float v2 = c1[j][2] + b0v, v3 = c1[j][3] + b1v;
                g[p][0] = 0.5f * v0 * (1.f + erff(v0 * 0.70710678118654752f));
                g[p][1] = 0.5f * v1 * (1.f + erff(v1 * 0.70710678118654752f));
                g[p][2] = 0.5f * v2 * (1.f + erff(v2 * 0.70710678118654752f));
                g[p][3] = 0.5f * v3 * (1.f + erff(v3 * 0.70710678118654752f));
            }
            pa[t][0] = packbf(g[0][0], g[0][1]);
            pa[t][1] = packbf(g[0][2], g[0][3]);
            pa[t][2] = packbf(g[1][0], g[1][1]);
            pa[t][3] = packbf(g[1][2], g[1][3]);
        }

        // fc2 partial: accumulate over this 64-wide hidden chunk
#pragma unroll
        for (int u2 = 0; u2 < 2; u2++)
#pragma unroll
            for (int j2 = 0; j2 < 16; j2++) {
                const uint4 B = g_wfc2p[(j2 * 16 + nc * 2 + u2) * 32 + lane];
                mma16816(hacc[j2], pa[2*u2],     B.x, B.y);
                mma16816(hacc[j2], pa[2*u2 + 1], B.z, B.w);
            }
    }

    // residual read-modify-write, direct to global (block owns these tokens)
    {
        float* base0 = io + (tok0 + warp * 16 + r) * EDIM;
        float* base1 = base0 + 8 * EDIM;
#pragma unroll
        for (int j2 = 0; j2 < 16; j2++) {
            const int col = j2 * 8 + c2;
            const float b0v = fc2_b[col], b1v = fc2_b[col + 1];
            float2 t0 = *(float2*)(base0 + col);
            t0.x += hacc[j2][0] + b0v;
            t0.y += hacc[j2][1] + b1v;
            *(float2*)(base0 + col) = t0;
            float2 t1 = *(float2*)(base1 + col);
            t1.x += hacc[j2][2] + b0v;
            t1.y += hacc[j2][3] + b1v;
            *(float2*)(base1 + col) = t1;
        }
    }
}

extern "C" void kernel_launch(void* const* d_in, const int* in_sizes, int n_in,
                              void* d_out, int out_size)
{
    const float* x      = (const float*)d_in[0];
    const float* qkv_w  = (const float*)d_in[1];
    const float* qkv_b  = (const float*)d_in[2];
    const float* proj_w = (const float*)d_in[3];
    const float* proj_b = (const float*)d_in[4];
    const float* ln1_s  = (const float*)d_in[5];
    const float* ln1_b  = (const float*)d_in[6];
    const float* ln2_s  = (const float*)d_in[7];
    const float* ln2_b  = (const float*)d_in[8];
    const float* fc1_w  = (const float*)d_in[9];
    const float* fc1_b  = (const float*)d_in[10];
    const float* fc2_w  = (const float*)d_in[11];
    const float* fc2_b  = (const float*)d_in[12];
    float* out = (float*)d_out;

    cudaFuncSetAttribute(attn_kernel, cudaFuncAttributeMaxDynamicSharedMemorySize, SM1_BYTES);
    cudaFuncSetAttribute(mlp_kernel,  cudaFuncAttributeMaxDynamicSharedMemorySize, SM2_BYTES);

    conv_attn<<<256, 256>>>(qkv_w, proj_w);
    conv_fc1p<<<128, 256>>>(fc1_w);
    conv_fc2p<<<128, 256>>>(fc2_w);
    attn_kernel<<<4096, 256, SM1_BYTES>>>(x, qkv_b, proj_b, ln1_s, ln1_b, out);
    mlp_kernel<<<2048, 256, SM2_BYTES>>>(out, ln2_s, ln2_b, fc1_b, fc2_b);
}

// round 10
// speedup vs baseline: 4.9481x; 1.0825x over previous
#include <cuda_runtime.h>
#include <cuda_bf16.h>
#include <math.h>
#include <stdint.h>

#define BATCH  8
#define FDIM   512
#define KDIM   64
#define EDIM   128
#define NHEAD  4
#define LWIN   64
#define FFI    128
#define NWIN   4
#define QK_SCALE 0.17677669529663687f
#define LN_EPS 1e-5f

__device__ __nv_bfloat16 g_wqkv[384 * 128];
__device__ __nv_bfloat16 g_wproj[128 * 128];
// fragment-packed fc weights: one uint4 = {b0(kt even), b1(kt even), b0(kt odd), b1(kt odd)}
// both are chunk-contiguous: records [nc*1024, (nc+1)*1024) cover hidden units [nc*64,(nc+1)*64)
__device__ uint4 g_wfc1p[8192];   // 512x128
__device__ uint4 g_wfc2p[8192];   // 128x512

__device__ __forceinline__ uint32_t sa(const void* p) {
    return (uint32_t)__cvta_generic_to_shared(p);
}
__device__ __forceinline__ void ldmx4(uint32_t (&r)[4], uint32_t a) {
    asm volatile("ldmatrix.sync.aligned.m8n8.x4.shared.b16 {%0,%1,%2,%3}, [%4];"
                 : "=r"(r[0]), "=r"(r[1]), "=r"(r[2]), "=r"(r[3]) : "r"(a));
}
__device__ __forceinline__ void ldmx2(uint32_t (&r)[2], uint32_t a) {
    asm volatile("ldmatrix.sync.aligned.m8n8.x2.shared.b16 {%0,%1}, [%2];"
                 : "=r"(r[0]), "=r"(r[1]) : "r"(a));
}
__device__ __forceinline__ void ldmx2t(uint32_t (&r)[2], uint32_t a) {
    asm volatile("ldmatrix.sync.aligned.m8n8.x2.trans.shared.b16 {%0,%1}, [%2];"
                 : "=r"(r[0]), "=r"(r[1]) : "r"(a));
}
__device__ __forceinline__ void mma16816(float (&d)[4], const uint32_t (&A)[4],
                                         uint32_t b0, uint32_t b1) {
    asm volatile("mma.sync.aligned.m16n8k16.row.col.f32.bf16.bf16.f32 "
                 "{%0,%1,%2,%3},{%4,%5,%6,%7},{%8,%9},{%0,%1,%2,%3};"
                 : "+f"(d[0]), "+f"(d[1]), "+f"(d[2]), "+f"(d[3])
                 : "r"(A[0]), "r"(A[1]), "r"(A[2]), "r"(A[3]), "r"(b0), "r"(b1));
}
__device__ __forceinline__ uint32_t packbf(float lo, float hi) {
    __nv_bfloat162 t = __floats2bfloat162_rn(lo, hi);
    return *reinterpret_cast<uint32_t*>(&t);
}

// ---- weight conversion / packing kernels (once per launch) ----
__global__ void conv_attn(const float* __restrict__ a, const float* __restrict__ b) {
    int i = blockIdx.x * 256 + threadIdx.x;   // 256 blocks -> 65536
    if (i < 49152) g_wqkv[i] = __float2bfloat16_rn(a[i]);
    else           g_wproj[i - 49152] = __float2bfloat16_rn(b[i - 49152]);
}
// fc1 (512x128): record (jg*4+u)*32+lane, jg in [0,64) = hidden n8 tile.
// chunk nc covers jg in [nc*8,(nc+1)*8) -> records [nc*1024,(nc+1)*1024).
__global__ void conv_fc1p(const float* __restrict__ w) {
    int tid = blockIdx.x * 256 + threadIdx.x;    // 128 blocks -> 32768
    int e = tid & 3, lane = (tid >> 2) & 31, u = (tid >> 7) & 3, jg = tid >> 9;
    int r = lane >> 2, c2 = (lane & 3) * 2;
    int row = jg * 8 + r;
    int cb = 32 * u + (e >> 1) * 16 + (e & 1) * 8 + c2;
    __nv_bfloat16* dst = (__nv_bfloat16*)g_wfc1p;
    dst[tid * 2]     = __float2bfloat16_rn(w[row * 128 + cb]);
    dst[tid * 2 + 1] = __float2bfloat16_rn(w[row * 128 + cb + 1]);
}
// fc2 (128x512): record (u*16+jg)*32+lane, u in [0,16) = k32 pair index.
// chunk nc covers u in {2nc,2nc+1} -> records [nc*1024,(nc+1)*1024),
// in-chunk order (u2*16+j2)*32+lane which is exactly the compute read order.
__global__ void conv_fc2p(const float* __restrict__ w) {
    int tid = blockIdx.x * 256 + threadIdx.x;    // 128 blocks -> 32768
    int e = tid & 3, lane = (tid >> 2) & 31, u = (tid >> 7) & 15, jg = tid >> 11;
    int r = lane >> 2, c2 = (lane & 3) * 2;
    int row = jg * 8 + r;
    int cb = 32 * u + (e >> 1) * 16 + (e & 1) * 8 + c2;
    int rec = (u * 16 + jg) * 32 + lane;
    __nv_bfloat16* dst = (__nv_bfloat16*)g_wfc2p;
    dst[(rec * 4 + e) * 2]     = __float2bfloat16_rn(w[row * 512 + cb]);
    dst[(rec * 4 + e) * 2 + 1] = __float2bfloat16_rn(w[row * 512 + cb + 1]);
}

// ============================================================================
// Kernel 1: shift + partition + LN1 + QKV + masked attn + proj + residual.
// 1 block = 1 window (64 tokens), 256 threads = 8 warps.  (round-6 exact)
// ============================================================================
#define S1 136
#define SM1_BYTES (5 * 64 * 136 * 2)

__global__ __launch_bounds__(256)
void attn_kernel(const float* __restrict__ x,
                 const float* __restrict__ qkv_b,
                 const float* __restrict__ proj_b,
                 const float* __restrict__ ln1_s,
                 const float* __restrict__ ln1_b,
                 float* __restrict__ out)
{
    extern __shared__ char smem[];
    __nv_bfloat16* XN = (__nv_bfloat16*)smem;
    __nv_bfloat16* QS = XN + 64 * S1;
    __nv_bfloat16* KS = QS + 64 * S1;
    __nv_bfloat16* VS = KS + 64 * S1;
    __nv_bfloat16* AO = VS + 64 * S1;
    float* OUTS = (float*)smem;

    const int tid  = threadIdx.x;
    const int lane = tid & 31;
    const int warp = tid >> 5;
    const int n  = blockIdx.x;
    const int wi = n & (NWIN - 1);
    const int fi = (n >> 2) & (FFI - 1);
    const int b  = n >> 9;

    const int r  = lane >> 2;
    const int c2 = (lane & 3) * 2;
    const int arow  = lane & 15;
    const int acol8 = (lane >> 4) * 8;

    // Phase A: gather (roll -2 along frames) + LN1 -> XN (bf16)
    {
        const int l = tid >> 2;
        const int q = tid & 3;
        const int tp = l >> 4, w16 = l & 15;
        int srcf = fi * 4 + tp + 2;
        if (srcf >= FDIM) srcf -= FDIM;
        const int kk = wi * 16 + w16;
        const float* xp = x + (((size_t)b * FDIM + srcf) * KDIM + kk) * EDIM + q * 32;
        float v[32];
#pragma unroll
        for (int i = 0; i < 8; i++) {
            float4 t = reinterpret_cast<const float4*>(xp)[i];
            v[4*i] = t.x; v[4*i+1] = t.y; v[4*i+2] = t.z; v[4*i+3] = t.w;
        }
        float s1 = 0.f, s2 = 0.f;
#pragma unroll
        for (int i = 0; i < 32; i++) { s1 += v[i]; s2 += v[i] * v[i]; }
        s1 += __shfl_xor_sync(0xffffffffu, s1, 1);
        s2 += __shfl_xor_sync(0xffffffffu, s2, 1);
        s1 += __shfl_xor_sync(0xffffffffu, s1, 2);
        s2 += __shfl_xor_sync(0xffffffffu, s2, 2);
        const float mean = s1 * (1.f / 128.f);
        const float rstd = rsqrtf(s2 * (1.f / 128.f) - mean * mean + LN_EPS);
#pragma unroll
        for (int i = 0; i < 16; i++) {
            const int c = q * 32 + 2 * i;
            float a0 = (v[2*i]   - mean) * rstd * ln1_s[c]     + ln1_b[c];
            float a1 = (v[2*i+1] - mean) * rstd * ln1_s[c + 1] + ln1_b[c + 1];
            *(uint32_t*)&XN[l * S1 + c] = packbf(a0, a1);
        }
    }
    __syncthreads();

    // Phase B: QKV GEMM, 3 passes of N=128, each warp owns a 16-wide n slice
    {
        const int nrow0 = warp * 16;
#pragma unroll
        for (int p = 0; p < 3; p++) {
            float acc[4][2][4];
#pragma unroll
            for (int mt = 0; mt < 4; mt++)
#pragma unroll
                for (int j = 0; j < 2; j++)
#pragma unroll
                    for (int e = 0; e < 4; e++) acc[mt][j][e] = 0.f;
            const __nv_bfloat16* Wg = g_wqkv + (size_t)(p * 128 + nrow0) * 128;
#pragma unroll
            for (int kt = 0; kt < 8; kt++) {
                uint32_t B0[2], B1[2];
#pragma unroll
                for (int j = 0; j < 2; j++) {
                    const __nv_bfloat16* bp = Wg + (j * 8 + r) * 128 + kt * 16 + c2;
                    B0[j] = *reinterpret_cast<const uint32_t*>(bp);
                    B1[j] = *reinterpret_cast<const uint32_t*>(bp + 8);
                }
#pragma unroll
                for (int mt = 0; mt < 4; mt++) {
                    uint32_t A[4];
                    ldmx4(A, sa(&XN[(mt * 16 + arow) * S1 + kt * 16 + acol8]));
                    mma16816(acc[mt][0], A, B0[0], B1[0]);
                    mma16816(acc[mt][1], A, B0[1], B1[1]);
                }
            }
            __nv_bfloat16* dst = (p == 0) ? QS : (p == 1) ? KS : VS;
#pragma unroll
            for (int mt = 0; mt < 4; mt++)
#pragma unroll
                for (int j = 0; j < 2; j++) {
                    const int col = nrow0 + j * 8 + c2;
                    const float b0v = qkv_b[p * 128 + col];
                    const float b1v = qkv_b[p * 128 + col + 1];
                    float v00 = acc[mt][j][0] + b0v, v01 = acc[mt][j][1] + b1v;
                    float v10 = acc[mt][j][2] + b0v, v11 = acc[mt][j][3] + b1v;
                    if (p == 0) { v00 *= QK_SCALE; v01 *= QK_SCALE; v10 *= QK_SCALE; v11 *= QK_SCALE; }
                    *(uint32_t*)&dst[(mt * 16 + r) * S1 + col]     = packbf(v00, v01);
                    *(uint32_t*)&dst[(mt * 16 + r + 8) * S1 + col] = packbf(v10, v11);
                }
        }
    }
    __syncthreads();

    // Phase C: scores + mask + softmax + PV, all in fragments.
    {
        const int h  = warp >> 1;
        const int m0 = (warp & 1) * 32;
        const bool maskwin = (fi == FFI - 1);

        uint32_t qa[2][2][4];
#pragma unroll
        for (int mt = 0; mt < 2; mt++)
#pragma unroll
            for (int kt = 0; kt < 2; kt++)
                ldmx4(qa[mt][kt], sa(&QS[(m0 + mt * 16 + arow) * S1 + h * 32 + kt * 16 + acol8]));

        float s[2][8][4];
#pragma unroll
        for (int mt = 0; mt < 2; mt++)
#pragma unroll
            for (int j = 0; j < 8; j++)
#pragma unroll
                for (int e = 0; e < 4; e++) s[mt][j][e] = 0.f;

#pragma unroll
        for (int j = 0; j < 8; j++)
#pragma unroll
            for (int kt = 0; kt < 2; kt++) {
                uint32_t kb[2];
                ldmx2(kb, sa(&KS[(j * 8 + (lane & 7)) * S1 + h * 32 + kt * 16 + ((lane >> 3) & 1) * 8]));
                mma16816(s[0][j], qa[0][kt], kb[0], kb[1]);
                mma16816(s[1][j], qa[1][kt], kb[0], kb[1]);
            }

#pragma unroll
        for (int mt = 0; mt < 2; mt++) {
            const int ra = m0 + mt * 16 + r;
            const int rb = ra + 8;
            const bool qah = (ra < 32), qbh = (rb < 32);
            float mxa = -1e30f, mxb = -1e30f;
#pragma unroll
            for (int j = 0; j < 8; j++) {
                const bool cq = (j < 4);
                float* v = s[mt][j];
                if (maskwin && (qah != cq)) { v[0] = -10000.f; v[1] = -10000.f; }
                else { if (v[0] == 0.f) v[0] = -10000.f; if (v[1] == 0.f) v[1] = -10000.f; }
                if (maskwin && (qbh != cq)) { v[2] = -10000.f; v[3] = -10000.f; }
                else { if (v[2] == 0.f) v[2] = -10000.f; if (v[3] == 0.f) v[3] = -10000.f; }
                mxa = fmaxf(mxa, fmaxf(v[0], v[1]));
                mxb = fmaxf(mxb, fmaxf(v[2], v[3]));
            }
            mxa = fmaxf(mxa, __shfl_xor_sync(0xffffffffu, mxa, 1));
            mxa = fmaxf(mxa, __shfl_xor_sync(0xffffffffu, mxa, 2));
            mxb = fmaxf(mxb, __shfl_xor_sync(0xffffffffu, mxb, 1));
            mxb = fmaxf(mxb, __shfl_xor_sync(0xffffffffu, mxb, 2));
            float sma = 0.f, smb = 0.f;
#pragma unroll
            for (int j = 0; j < 8; j++) {
                float* v = s[mt][j];
                v[0] = __expf(v[0] - mxa); v[1] = __expf(v[1] - mxa);
                v[2] = __expf(v[2] - mxb); v[3] = __expf(v[3] - mxb);
                sma += v[0] + v[1]; smb += v[2] + v[3];
            }
            sma += __shfl_xor_sync(0xffffffffu, sma, 1);
            sma += __shfl_xor_sync(0xffffffffu, sma, 2);
            smb += __shfl_xor_sync(0xffffffffu, smb, 1);
            smb += __shfl_xor_sync(0xffffffffu, smb, 2);
            const float ia = 1.f / sma, ib = 1.f / smb;
#pragma unroll
            for (int j = 0; j < 8; j++) {
                float* v = s[mt][j];
                v[0] *= ia; v[1] *= ia; v[2] *= ib; v[3] *= ib;
            }
        }

        float o[2][4][4];
#pragma unroll
        for (int mt = 0; mt < 2; mt++)
#pragma unroll
            for (int j2 = 0; j2 < 4; j2++)
#pragma unroll
                for (int e = 0; e < 4; e++) o[mt][j2][e] = 0.f;
#pragma unroll
        for (int kt = 0; kt < 4; kt++) {
            uint32_t pa[2][4];
#pragma unroll
            for (int mt = 0; mt < 2; mt++) {
                pa[mt][0] = packbf(s[mt][2*kt][0],   s[mt][2*kt][1]);
                pa[mt][1] = packbf(s[mt][2*kt][2],   s[mt][2*kt][3]);
                pa[mt][2] = packbf(s[mt][2*kt+1][0], s[mt][2*kt+1][1]);
                pa[mt][3] = packbf(s[mt][2*kt+1][2], s[mt][2*kt+1][3]);
            }
#pragma unroll
            for (int j2 = 0; j2 < 4; j2++) {
                uint32_t vb[2];
                ldmx2t(vb, sa(&VS[(kt * 16 + arow) * S1 + h * 32 + j2 * 8]));
                mma16816(o[0][j2], pa[0], vb[0], vb[1]);
                mma16816(o[1][j2], pa[1], vb[0], vb[1]);
            }
        }
#pragma unroll
        for (int mt = 0; mt < 2; mt++)
#pragma unroll
            for (int j2 = 0; j2 < 4; j2++) {
                const int row = m0 + mt * 16 + r;
                const int col = h * 32 + j2 * 8 + c2;
                *(uint32_t*)&AO[row * S1 + col]       = packbf(o[mt][j2][0], o[mt][j2][1]);
                *(uint32_t*)&AO[(row + 8) * S1 + col] = packbf(o[mt][j2][2], o[mt][j2][3]);
            }
    }
    __syncthreads();

    // Phase D: proj (64x128x128) -> OUTS fp32
    {
        const int nrow0 = warp * 16;
        float acc[4][2][4];
#pragma unroll
        for (int mt = 0; mt < 4; mt++)
#pragma unroll
            for (int j = 0; j < 2; j++)
#pragma unroll
                for (int e = 0; e < 4; e++) acc[mt][j][e] = 0.f;
        const __nv_bfloat16* Wg = g_wproj + (size_t)nrow0 * 128;
#pragma unroll
        for (int kt = 0; kt < 8; kt++) {
            uint32_t B0[2], B1[2];
#pragma unroll
            for (int j = 0; j < 2; j++) {
                const __nv_bfloat16* bp = Wg + (j * 8 + r) * 128 + kt * 16 + c2;
                B0[j] = *reinterpret_cast<const uint32_t*>(bp);
                B1[j] = *reinterpret_cast<const uint32_t*>(bp + 8);
            }
#pragma unroll
            for (int mt = 0; mt < 4; mt++) {
                uint32_t A[4];
                ldmx4(A, sa(&AO[(mt * 16 + arow) * S1 + kt * 16 + acol8]));
                mma16816(acc[mt][0], A, B0[0], B1[0]);
                mma16816(acc[mt][1], A, B0[1], B1[1]);
            }
        }
        __syncthreads();
#pragma unroll
        for (int mt = 0; mt < 4; mt++)
#pragma unroll
            for (int j = 0; j < 2; j++) {
                const int col = nrow0 + j * 8 + c2;
                const float b0v = proj_b[col], b1v = proj_b[col + 1];
                *(float2*)&OUTS[(mt * 16 + r) * 132 + col] =
                    make_float2(acc[mt][j][0] + b0v, acc[mt][j][1] + b1v);
                *(float2*)&OUTS[(mt * 16 + r + 8) * 132 + col] =
                    make_float2(acc[mt][j][2] + b0v, acc[mt][j][3] + b1v);
            }
    }
    __syncthreads();

    // Phase E: roll(+2 along window tokens) + window reverse + residual
    {
        const int lp = tid >> 2;
        const int q  = tid & 3;
        const int tp = lp >> 4, w16 = lp & 15;
        const int lsrc = (lp - 2 + LWIN) & (LWIN - 1);
        const int frame = fi * 4 + tp;
        const int kk = wi * 16 + w16;
        const size_t base = (((size_t)b * FDIM + frame) * KDIM + kk) * EDIM + q * 32;
        const float* xp = x + base;
        float* op = out + base;
#pragma unroll
        for (int i = 0; i < 8; i++) {
            float4 t = reinterpret_cast<const float4*>(xp)[i];
            const int c = q * 32 + 4 * i;
            t.x += OUTS[lsrc * 132 + c];
            t.y += OUTS[lsrc * 132 + c + 1];
            t.z += OUTS[lsrc * 132 + c + 2];
            t.w += OUTS[lsrc * 132 + c + 3];
            reinterpret_cast<float4*>(op)[i] = t;
        }
    }
}

// ============================================================================
// Kernel 2: LN2 + fc1 + GELU + fc2 + residual. 128 tokens/block, 8 warps.
// Weights staged into smem per block (plain LDG.128/STS.128); both packed
// arrays are chunk-contiguous so staging is two linear copies.
// ============================================================================
#define S2 136
#define XS_BYTES (128 * 136 * 2)           // 34816
#define WCHUNK_U4 2048                      // 1024 fc1 + 1024 fc2 records
#define SM2_BYTES (XS_BYTES + WCHUNK_U4 * 16)

__global__ __launch_bounds__(256)
void mlp_kernel(float* __restrict__ io,
                const float* __restrict__ ln2_s,
                const float* __restrict__ ln2_b,
                const float* __restrict__ fc1_b,
                const float* __restrict__ fc2_b)
{
    extern __shared__ char smem[];
    __nv_bfloat16* XS = (__nv_bfloat16*)smem;                 // [128][S2]
    uint4* WB1 = (uint4*)(smem + XS_BYTES);                   // 1024 records
    uint4* WB2 = WB1 + 1024;                                  // 1024 records

    const int tid  = threadIdx.x;
    const int lane = tid & 31;
    const int warp = tid >> 5;
    const size_t tok0 = (size_t)blockIdx.x * 128;

    const int r  = lane >> 2;
    const int c2 = (lane & 3) * 2;
    const int arow  = lane & 15;
    const int acol8 = (lane >> 4) * 8;

    // LN2 for this warp's 16 tokens (2 lanes per token) -> XS slice
    {
        const int l = warp * 16 + (lane >> 1);
        const int q = lane & 1;
        const float* xp = io + (tok0 + l) * EDIM + q * 64;
        float v[64];
#pragma unroll
        for (int i = 0; i < 16; i++) {
            float4 t = reinterpret_cast<const float4*>(xp)[i];
            v[4*i] = t.x; v[4*i+1] = t.y; v[4*i+2] = t.z; v[4*i+3] = t.w;
        }
        float s1 = 0.f, s2 = 0.f;
#pragma unroll
        for (int i = 0; i < 64; i++) { s1 += v[i]; s2 += v[i] * v[i]; }
        s1 += __shfl_xor_sync(0xffffffffu, s1, 1);
        s2 += __shfl_xor_sync(0xffffffffu, s2, 1);
        const float mean = s1 * (1.f / 128.f);
        const float rstd = rsqrtf(s2 * (1.f / 128.f) - mean * mean + LN_EPS);
#pragma unroll
        for (int i = 0; i < 32; i++) {
            const int c = q * 64 + 2 * i;
            float a0 = (v[2*i]   - mean) * rstd * ln2_s[c]     + ln2_b[c];
            float a1 = (v[2*i+1] - mean) * rstd * ln2_s[c + 1] + ln2_b[c + 1];
            *(uint32_t*)&XS[l * S2 + c] = packbf(a0, a1);
        }
    }
    __syncwarp();

    // A fragments register-resident (16 tokens x 128 K)
    uint32_t a[8][4];
#pragma unroll
    for (int kt = 0; kt < 8; kt++)
        ldmx4(a[kt], sa(&XS[(warp * 16 + arow) * S2 + kt * 16 + acol8]));

    float hacc[16][4];
#pragma unroll
    for (int j2 = 0; j2 < 16; j2++)
#pragma unroll
        for (int e = 0; e < 4; e++) hacc[j2][e] = 0.f;

    for (int nc = 0; nc < 8; nc++) {
        // stage this chunk's weights into smem (both arrays chunk-contiguous)
        __syncthreads();
#pragma unroll
        for (int i = 0; i < 4; i++) {
            const int idx = i * 256 + tid;          // 0..1023
            WB1[idx] = g_wfc1p[nc * 1024 + idx];
            WB2[idx] = g_wfc2p[nc * 1024 + idx];
        }
        __syncthreads();

        // fc1: this warp's 16 tokens x 64 hidden units
        float c1[8][4];
#pragma unroll
        for (int j = 0; j < 8; j++)
#pragma unroll
            for (int e = 0; e < 4; e++) c1[j][e] = 0.f;
#pragma unroll
        for (int u = 0; u < 4; u++)
#pragma unroll
            for (int j = 0; j < 8; j++) {
                const uint4 B = WB1[(j * 4 + u) * 32 + lane];
                mma16816(c1[j], a[2*u],     B.x, B.y);
                mma16816(c1[j], a[2*u + 1], B.z, B.w);
            }

        // bias + exact GELU + repack C-frag -> A-frag (registers only)
        uint32_t pa[4][4];
#pragma unroll
        for (int t = 0; t < 4; t++) {
#pragma unroll
            for (int p = 0; p < 2; p++) {
                const int j = 2 * t + p;
                const int gn = nc * 64 + j * 8 + c2;
                const float b0v = fc1_b[gn], b1v = fc1_b[gn + 1];
                float v0 = c1[j][0] + b0v, v1 = c1[j][1] + b1v;
                float v2 = c1[j][2] + b0v, v3 = c1[j][3] + b1v;
                v0 = 0.5f * v0 * (1.f + erff(v0 * 0.70710678118654752f));
                v1 = 0.5f * v1 * (1.f + erff(v1 * 0.70710678118654752f));
                v2 = 0.5f * v2 * (1.f + erff(v2 * 0.70710678118654752f));
                v3 = 0.5f * v3 * (1.f + erff(v3 * 0.70710678118654752f));
                pa[t][2*p]     = packbf(v0, v1);
                pa[t][2*p + 1] = packbf(v2, v3);
            }
        }

        // fc2 partial accumulate over this 64-wide hidden chunk
#pragma unroll
        for (int u2 = 0; u2 < 2; u2++)
#pragma unroll
            for (int j2 = 0; j2 < 16; j2++) {
                const uint4 B = WB2[(u2 * 16 + j2) * 32 + lane];
                mma16816(hacc[j2], pa[2*u2],     B.x, B.y);
                mma16816(hacc[j2], pa[2*u2 + 1], B.z, B.w);
            }
    }

    // residual read-modify-write, direct to global (block owns these tokens)
    {
        float* base0 = io + (tok0 + warp * 16 + r) * EDIM;
        float* base1 = base0 + 8 * EDIM;
#pragma unroll
        for (int j2 = 0; j2 < 16; j2++) {
            const int col = j2 * 8 + c2;
            const float b0v = fc2_b[col], b1v = fc2_b[col + 1];
            float2 t0 = *(float2*)(base0 + col);
            t0.x += hacc[j2][0] + b0v;
            t0.y += hacc[j2][1] + b1v;
            *(float2*)(base0 + col) = t0;
            float2 t1 = *(float2*)(base1 + col);
            t1.x += hacc[j2][2] + b0v;
            t1.y += hacc[j2][3] + b1v;
            *(float2*)(base1 + col) = t1;
        }
    }
}

extern "C" void kernel_launch(void* const* d_in, const int* in_sizes, int n_in,
                              void* d_out, int out_size)
{
    const float* x      = (const float*)d_in[0];
    const float* qkv_w  = (const float*)d_in[1];
    const float* qkv_b  = (const float*)d_in[2];
    const float* proj_w = (const float*)d_in[3];
    const float* proj_b = (const float*)d_in[4];
    const float* ln1_s  = (const float*)d_in[5];
    const float* ln1_b  = (const float*)d_in[6];
    const float* ln2_s  = (const float*)d_in[7];
    const float* ln2_b  = (const float*)d_in[8];
    const float* fc1_w  = (const float*)d_in[9];
    const float* fc1_b  = (const float*)d_in[10];
    const float* fc2_w  = (const float*)d_in[11];
    const float* fc2_b  = (const float*)d_in[12];
    float* out = (float*)d_out;

    cudaFuncSetAttribute(attn_kernel, cudaFuncAttributeMaxDynamicSharedMemorySize, SM1_BYTES);
    cudaFuncSetAttribute(mlp_kernel,  cudaFuncAttributeMaxDynamicSharedMemorySize, SM2_BYTES);

    conv_attn<<<256, 256>>>(qkv_w, proj_w);
    conv_fc1p<<<128, 256>>>(fc1_w);
    conv_fc2p<<<128, 256>>>(fc2_w);
    attn_kernel<<<4096, 256, SM1_BYTES>>>(x, qkv_b, proj_b, ln1_s, ln1_b, out);
    mlp_kernel<<<2048, 256, SM2_BYTES>>>(out, ln2_s, ln2_b, fc1_b, fc2_b);
}

// round 12
// speedup vs baseline: 5.4075x; 1.0928x over previous
#include <cuda_runtime.h>
#include <cuda_bf16.h>
#include <math.h>
#include <stdint.h>

#define BATCH  8
#define FDIM   512
#define KDIM   64
#define EDIM   128
#define NHEAD  4
#define LWIN   64
#define FFI    128
#define NWIN   4
#define QK_SCALE 0.17677669529663687f
#define LN_EPS 1e-5f

// fragment-packed weights: one uint4 = {b0(kt even), b1(kt even), b0(kt odd), b1(kt odd)}
__device__ uint4 g_wqkvp[6144];   // 384x128
__device__ uint4 g_wprojp[2048];  // 128x128
__device__ uint4 g_wfc1p[8192];   // 512x128, chunk-contiguous
__device__ uint4 g_wfc2p[8192];   // 128x512, chunk-contiguous

__device__ __forceinline__ uint32_t sa(const void* p) {
    return (uint32_t)__cvta_generic_to_shared(p);
}
__device__ __forceinline__ void ldmx4(uint32_t (&r)[4], uint32_t a) {
    asm volatile("ldmatrix.sync.aligned.m8n8.x4.shared.b16 {%0,%1,%2,%3}, [%4];"
                 : "=r"(r[0]), "=r"(r[1]), "=r"(r[2]), "=r"(r[3]) : "r"(a));
}
__device__ __forceinline__ void ldmx2(uint32_t (&r)[2], uint32_t a) {
    asm volatile("ldmatrix.sync.aligned.m8n8.x2.shared.b16 {%0,%1}, [%2];"
                 : "=r"(r[0]), "=r"(r[1]) : "r"(a));
}
__device__ __forceinline__ void ldmx2t(uint32_t (&r)[2], uint32_t a) {
    asm volatile("ldmatrix.sync.aligned.m8n8.x2.trans.shared.b16 {%0,%1}, [%2];"
                 : "=r"(r[0]), "=r"(r[1]) : "r"(a));
}
__device__ __forceinline__ void mma16816(float (&d)[4], const uint32_t (&A)[4],
                                         uint32_t b0, uint32_t b1) {
    asm volatile("mma.sync.aligned.m16n8k16.row.col.f32.bf16.bf16.f32 "
                 "{%0,%1,%2,%3},{%4,%5,%6,%7},{%8,%9},{%0,%1,%2,%3};"
                 : "+f"(d[0]), "+f"(d[1]), "+f"(d[2]), "+f"(d[3])
                 : "r"(A[0]), "r"(A[1]), "r"(A[2]), "r"(A[3]), "r"(b0), "r"(b1));
}
__device__ __forceinline__ uint32_t packbf(float lo, float hi) {
    __nv_bfloat162 t = __floats2bfloat162_rn(lo, hi);
    return *reinterpret_cast<uint32_t*>(&t);
}

// ---- weight packers (once per launch; destinations named INSIDE device code) ----
// K-major rows x 128: uint4 record (jg*4+u)*32+lane; element e = bf16x2 at
// (row = jg*8+r, col = 32u + (e>>1)*16 + (e&1)*8 + c2).
__global__ void pack_qkvp(const float* __restrict__ w) {
    int tid = blockIdx.x * 256 + threadIdx.x;    // 96 blocks -> 24576
    int e = tid & 3, lane = (tid >> 2) & 31, u = (tid >> 7) & 3, jg = tid >> 9;
    int r = lane >> 2, c2 = (lane & 3) * 2;
    int row = jg * 8 + r;
    int cb = 32 * u + (e >> 1) * 16 + (e & 1) * 8 + c2;
    __nv_bfloat16* dst = (__nv_bfloat16*)g_wqkvp;
    dst[tid * 2]     = __float2bfloat16_rn(w[row * 128 + cb]);
    dst[tid * 2 + 1] = __float2bfloat16_rn(w[row * 128 + cb + 1]);
}
__global__ void pack_projp(const float* __restrict__ w) {
    int tid = blockIdx.x * 256 + threadIdx.x;    // 32 blocks -> 8192
    int e = tid & 3, lane = (tid >> 2) & 31, u = (tid >> 7) & 3, jg = tid >> 9;
    int r = lane >> 2, c2 = (lane & 3) * 2;
    int row = jg * 8 + r;
    int cb = 32 * u + (e >> 1) * 16 + (e & 1) * 8 + c2;
    __nv_bfloat16* dst = (__nv_bfloat16*)g_wprojp;
    dst[tid * 2]     = __float2bfloat16_rn(w[row * 128 + cb]);
    dst[tid * 2 + 1] = __float2bfloat16_rn(w[row * 128 + cb + 1]);
}
__global__ void conv_fc1p(const float* __restrict__ w) {
    int tid = blockIdx.x * 256 + threadIdx.x;    // 128 blocks -> 32768
    int e = tid & 3, lane = (tid >> 2) & 31, u = (tid >> 7) & 3, jg = tid >> 9;
    int r = lane >> 2, c2 = (lane & 3) * 2;
    int row = jg * 8 + r;
    int cb = 32 * u + (e >> 1) * 16 + (e & 1) * 8 + c2;
    __nv_bfloat16* dst = (__nv_bfloat16*)g_wfc1p;
    dst[tid * 2]     = __float2bfloat16_rn(w[row * 128 + cb]);
    dst[tid * 2 + 1] = __float2bfloat16_rn(w[row * 128 + cb + 1]);
}
__global__ void conv_fc2p(const float* __restrict__ w) {
    int tid = blockIdx.x * 256 + threadIdx.x;    // 128 blocks -> 32768
    int e = tid & 3, lane = (tid >> 2) & 31, u = (tid >> 7) & 15, jg = tid >> 11;
    int r = lane >> 2, c2 = (lane & 3) * 2;
    int row = jg * 8 + r;
    int cb = 32 * u + (e >> 1) * 16 + (e & 1) * 8 + c2;
    int rec = (u * 16 + jg) * 32 + lane;
    __nv_bfloat16* dst = (__nv_bfloat16*)g_wfc2p;
    dst[(rec * 4 + e) * 2]     = __float2bfloat16_rn(w[row * 512 + cb]);
    dst[(rec * 4 + e) * 2 + 1] = __float2bfloat16_rn(w[row * 512 + cb + 1]);
}

// ============================================================================
// Kernel 1: TWO windows per block (M=128). 256 threads = 8 warps.
// GEMM phases: warp = m32 x n64, packed-uint4 B from global.
// Attention phase: warp = (head, m32-half), looped over the 2 windows.
// smem: XN,QS,KS,VS,AO bf16 [128][136]; OUTS f32 [128][132] aliases XN+QS.
// ============================================================================
#define S1 136
#define SM1_BYTES (5 * 128 * 136 * 2)

__global__ __launch_bounds__(256)
void attn_kernel(const float* __restrict__ x,
                 const float* __restrict__ qkv_b,
                 const float* __restrict__ proj_b,
                 const float* __restrict__ ln1_s,
                 const float* __restrict__ ln1_b,
                 float* __restrict__ out)
{
    extern __shared__ char smem[];
    __nv_bfloat16* XN = (__nv_bfloat16*)smem;
    __nv_bfloat16* QS = XN + 128 * S1;
    __nv_bfloat16* KS = QS + 128 * S1;
    __nv_bfloat16* VS = KS + 128 * S1;
    __nv_bfloat16* AO = VS + 128 * S1;
    float* OUTS = (float*)smem;   // [128][132] f32; spans XN+QS (dead by Phase D writes)

    const int tid  = threadIdx.x;
    const int lane = tid & 31;
    const int warp = tid >> 5;
    const int n  = blockIdx.x;            // 2048 blocks, 2 windows each
    const int wp = n & 1;                 // wi pair: windows wi=2wp, 2wp+1
    const int fi = (n >> 1) & (FFI - 1);
    const int b  = n >> 8;

    const int r  = lane >> 2;
    const int c2 = (lane & 3) * 2;
    const int arow  = lane & 15;
    const int acol8 = (lane >> 4) * 8;

    // GEMM-phase warp tiling: m32 (mh) x n64 (nh)
    const int mh = warp & 3;
    const int nh = warp >> 2;

    // Phase A: gather (roll -2 along frames) + LN1 -> XN (bf16), 2 thr/token
    {
        const int row = tid >> 1;          // 0..127
        const int q   = tid & 1;
        const int win = row >> 6;
        const int l   = row & 63;
        const int tp = l >> 4, w16 = l & 15;
        int srcf = fi * 4 + tp + 2;
        if (srcf >= FDIM) srcf -= FDIM;
        const int kk = (2 * wp + win) * 16 + w16;
        const float* xp = x + (((size_t)b * FDIM + srcf) * KDIM + kk) * EDIM + q * 64;
        float v[64];
#pragma unroll
        for (int i = 0; i < 16; i++) {
            float4 t = reinterpret_cast<const float4*>(xp)[i];
            v[4*i] = t.x; v[4*i+1] = t.y; v[4*i+2] = t.z; v[4*i+3] = t.w;
        }
        float s1 = 0.f, s2 = 0.f;
#pragma unroll
        for (int i = 0; i < 64; i++) { s1 += v[i]; s2 += v[i] * v[i]; }
        s1 += __shfl_xor_sync(0xffffffffu, s1, 1);
        s2 += __shfl_xor_sync(0xffffffffu, s2, 1);
        const float mean = s1 * (1.f / 128.f);
        const float rstd = rsqrtf(s2 * (1.f / 128.f) - mean * mean + LN_EPS);
#pragma unroll
        for (int ii = 0; ii < 8; ii++) {
            uint32_t w4[4];
#pragma unroll
            for (int k = 0; k < 4; k++) {
                const int i = ii * 4 + k;
                const int c = q * 64 + 2 * i;
                float a0 = (v[2*i]   - mean) * rstd * ln1_s[c]     + ln1_b[c];
                float a1 = (v[2*i+1] - mean) * rstd * ln1_s[c + 1] + ln1_b[c + 1];
                w4[k] = packbf(a0, a1);
            }
            *(uint4*)&XN[row * S1 + q * 64 + 8 * ii] =
                make_uint4(w4[0], w4[1], w4[2], w4[3]);
        }
    }
    __syncthreads();

    // Phase B: QKV GEMM (128x384x128). warp: m32 x n64, packed B LDG.128.
    {
#pragma unroll
        for (int p = 0; p < 3; p++) {
            float acc[2][8][4];
#pragma unroll
            for (int mt = 0; mt < 2; mt++)
#pragma unroll
                for (int j = 0; j < 8; j++)
#pragma unroll
                    for (int e = 0; e < 4; e++) acc[mt][j][e] = 0.f;
#pragma unroll
            for (int u = 0; u < 4; u++) {
                uint32_t Ae[2][4], Ao[2][4];
#pragma unroll
                for (int mt = 0; mt < 2; mt++) {
                    const int row = (mh * 2 + mt) * 16 + arow;
                    ldmx4(Ae[mt], sa(&XN[row * S1 + (2*u) * 16 + acol8]));
                    ldmx4(Ao[mt], sa(&XN[row * S1 + (2*u+1) * 16 + acol8]));
                }
#pragma unroll
                for (int j = 0; j < 8; j++) {
                    const uint4 B = g_wqkvp[(((p * 16 + nh * 8 + j) * 4 + u) * 32) + lane];
#pragma unroll
                    for (int mt = 0; mt < 2; mt++) {
                        mma16816(acc[mt][j], Ae[mt], B.x, B.y);
                        mma16816(acc[mt][j], Ao[mt], B.z, B.w);
                    }
                }
            }
            __nv_bfloat16* dst = (p == 0) ? QS : (p == 1) ? KS : VS;
#pragma unroll
            for (int mt = 0; mt < 2; mt++)
#pragma unroll
                for (int j = 0; j < 8; j++) {
                    const int col = nh * 64 + j * 8 + c2;
                    const float b0v = qkv_b[p * 128 + col];
                    const float b1v = qkv_b[p * 128 + col + 1];
                    float v00 = acc[mt][j][0] + b0v, v01 = acc[mt][j][1] + b1v;
                    float v10 = acc[mt][j][2] + b0v, v11 = acc[mt][j][3] + b1v;
                    if (p == 0) { v00 *= QK_SCALE; v01 *= QK_SCALE; v10 *= QK_SCALE; v11 *= QK_SCALE; }
                    const int row = (mh * 2 + mt) * 16 + r;
                    *(uint32_t*)&dst[row * S1 + col]       = packbf(v00, v01);
                    *(uint32_t*)&dst[(row + 8) * S1 + col] = packbf(v10, v11);
                }
        }
    }
    __syncthreads();

    // Phase C: scores + mask + softmax + PV (verified code, looped over windows)
    {
        const int h   = warp >> 1;
        const int m0w = (warp & 1) * 32;     // window-local m offset
        const bool maskwin = (fi == FFI - 1);

#pragma unroll
        for (int win = 0; win < 2; win++) {
            const int base = win * 64;

            uint32_t qa[2][2][4];
#pragma unroll
            for (int mt = 0; mt < 2; mt++)
#pragma unroll
                for (int kt = 0; kt < 2; kt++)
                    ldmx4(qa[mt][kt], sa(&QS[(base + m0w + mt * 16 + arow) * S1 + h * 32 + kt * 16 + acol8]));

            float s[2][8][4];
#pragma unroll
            for (int mt = 0; mt < 2; mt++)
#pragma unroll
                for (int j = 0; j < 8; j++)
#pragma unroll
                    for (int e = 0; e < 4; e++) s[mt][j][e] = 0.f;

#pragma unroll
            for (int j = 0; j < 8; j++)
#pragma unroll
                for (int kt = 0; kt < 2; kt++) {
                    uint32_t kb[2];
                    ldmx2(kb, sa(&KS[(base + j * 8 + (lane & 7)) * S1 + h * 32 + kt * 16 + ((lane >> 3) & 1) * 8]));
                    mma16816(s[0][j], qa[0][kt], kb[0], kb[1]);
                    mma16816(s[1][j], qa[1][kt], kb[0], kb[1]);
                }

#pragma unroll
            for (int mt = 0; mt < 2; mt++) {
                const int ra = m0w + mt * 16 + r;      // window-local rows
                const int rb = ra + 8;
                const bool qah = (ra < 32), qbh = (rb < 32);
                float mxa = -1e30f, mxb = -1e30f;
#pragma unroll
                for (int j = 0; j < 8; j++) {
                    const bool cq = (j < 4);
                    float* v = s[mt][j];
                    if (maskwin && (qah != cq)) { v[0] = -10000.f; v[1] = -10000.f; }
                    else { if (v[0] == 0.f) v[0] = -10000.f; if (v[1] == 0.f) v[1] = -10000.f; }
                    if (maskwin && (qbh != cq)) { v[2] = -10000.f; v[3] = -10000.f; }
                    else { if (v[2] == 0.f) v[2] = -10000.f; if (v[3] == 0.f) v[3] = -10000.f; }
                    mxa = fmaxf(mxa, fmaxf(v[0], v[1]));
                    mxb = fmaxf(mxb, fmaxf(v[2], v[3]));
                }
                mxa = fmaxf(mxa, __shfl_xor_sync(0xffffffffu, mxa, 1));
                mxa = fmaxf(mxa, __shfl_xor_sync(0xffffffffu, mxa, 2));
                mxb = fmaxf(mxb, __shfl_xor_sync(0xffffffffu, mxb, 1));
                mxb = fmaxf(mxb, __shfl_xor_sync(0xffffffffu, mxb, 2));
                float sma = 0.f, smb = 0.f;
#pragma unroll
                for (int j = 0; j < 8; j++) {
                    float* v = s[mt][j];
                    v[0] = __expf(v[0] - mxa); v[1] = __expf(v[1] - mxa);
                    v[2] = __expf(v[2] - mxb); v[3] = __expf(v[3] - mxb);
                    sma += v[0] + v[1]; smb += v[2] + v[3];
                }
                sma += __shfl_xor_sync(0xffffffffu, sma, 1);
                sma += __shfl_xor_sync(0xffffffffu, sma, 2);
                smb += __shfl_xor_sync(0xffffffffu, smb, 1);
                smb += __shfl_xor_sync(0xffffffffu, smb, 2);
                const float ia = 1.f / sma, ib = 1.f / smb;
#pragma unroll
                for (int j = 0; j < 8; j++) {
                    float* v = s[mt][j];
                    v[0] *= ia; v[1] *= ia; v[2] *= ib; v[3] *= ib;
                }
            }

            float o[2][4][4];
#pragma unroll
            for (int mt = 0; mt < 2; mt++)
#pragma unroll
                for (int j2 = 0; j2 < 4; j2++)
#pragma unroll
                    for (int e = 0; e < 4; e++) o[mt][j2][e] = 0.f;
#pragma unroll
            for (int kt = 0; kt < 4; kt++) {
                uint32_t pa[2][4];
#pragma unroll
                for (int mt = 0; mt < 2; mt++) {
                    pa[mt][0] = packbf(s[mt][2*kt][0],   s[mt][2*kt][1]);
                    pa[mt][1] = packbf(s[mt][2*kt][2],   s[mt][2*kt][3]);
                    pa[mt][2] = packbf(s[mt][2*kt+1][0], s[mt][2*kt+1][1]);
                    pa[mt][3] = packbf(s[mt][2*kt+1][2], s[mt][2*kt+1][3]);
                }
#pragma unroll
                for (int j2 = 0; j2 < 4; j2++) {
                    uint32_t vb[2];
                    ldmx2t(vb, sa(&VS[(base + kt * 16 + arow) * S1 + h * 32 + j2 * 8]));
                    mma16816(o[0][j2], pa[0], vb[0], vb[1]);
                    mma16816(o[1][j2], pa[1], vb[0], vb[1]);
                }
            }
#pragma unroll
            for (int mt = 0; mt < 2; mt++)
#pragma unroll
                for (int j2 = 0; j2 < 4; j2++) {
                    const int row = base + m0w + mt * 16 + r;
                    const int col = h * 32 + j2 * 8 + c2;
                    *(uint32_t*)&AO[row * S1 + col]       = packbf(o[mt][j2][0], o[mt][j2][1]);
                    *(uint32_t*)&AO[(row + 8) * S1 + col] = packbf(o[mt][j2][2], o[mt][j2][3]);
                }
        }
    }
    __syncthreads();

    // Phase D: proj (128x128x128). warp: m32 x n64, packed B LDG.128. -> OUTS
    {
        float acc[2][8][4];
#pragma unroll
        for (int mt = 0; mt < 2; mt++)
#pragma unroll
            for (int j = 0; j < 8; j++)
#pragma unroll
                for (int e = 0; e < 4; e++) acc[mt][j][e] = 0.f;
#pragma unroll
        for (int u = 0; u < 4; u++) {
            uint32_t Ae[2][4], Ao[2][4];
#pragma unroll
            for (int mt = 0; mt < 2; mt++) {
                const int row = (mh * 2 + mt) * 16 + arow;
                ldmx4(Ae[mt], sa(&AO[row * S1 + (2*u) * 16 + acol8]));
                ldmx4(Ao[mt], sa(&AO[row * S1 + (2*u+1) * 16 + acol8]));
            }
#pragma unroll
            for (int j = 0; j < 8; j++) {
                const uint4 B = g_wprojp[(((nh * 8 + j) * 4 + u) * 32) + lane];
#pragma unroll
                for (int mt = 0; mt < 2; mt++) {
                    mma16816(acc[mt][j], Ae[mt], B.x, B.y);
                    mma16816(acc[mt][j], Ao[mt], B.z, B.w);
                }
            }
        }
        __syncthreads();   // all QS-region reads done before OUTS overwrite
#pragma unroll
        for (int mt = 0; mt < 2; mt++)
#pragma unroll
            for (int j = 0; j < 8; j++) {
                const int col = nh * 64 + j * 8 + c2;
                const float b0v = proj_b[col], b1v = proj_b[col + 1];
                const int row = (mh * 2 + mt) * 16 + r;
                *(float2*)&OUTS[row * 132 + col] =
                    make_float2(acc[mt][j][0] + b0v, acc[mt][j][1] + b1v);
                *(float2*)&OUTS[(row + 8) * 132 + col] =
                    make_float2(acc[mt][j][2] + b0v, acc[mt][j][3] + b1v);
            }
    }
    __syncthreads();

    // Phase E: roll(+2 along window tokens) + window reverse + residual
    {
        const int lp  = tid >> 1;          // destination token 0..127
        const int q   = tid & 1;
        const int win = lp >> 6;
        const int l   = lp & 63;
        const int tp = l >> 4, w16 = l & 15;
        const int lsrc = win * 64 + ((l - 2 + LWIN) & (LWIN - 1));
        const int frame = fi * 4 + tp;
        const int kk = (2 * wp + win) * 16 + w16;
        const size_t base = (((size_t)b * FDIM + frame) * KDIM + kk) * EDIM + q * 64;
        const float* xp = x + base;
        float* op = out + base;
#pragma unroll
        for (int i = 0; i < 16; i++) {
            float4 t = reinterpret_cast<const float4*>(xp)[i];
            const int c = q * 64 + 4 * i;
            t.x += OUTS[lsrc * 132 + c];
            t.y += OUTS[lsrc * 132 + c + 1];
            t.z += OUTS[lsrc * 132 + c + 2];
            t.w += OUTS[lsrc * 132 + c + 3];
            reinterpret_cast<float4*>(op)[i] = t;
        }
    }
}

// ============================================================================
// Kernel 2: LN2 + fc1 + GELU + fc2 + residual. (round-10 exact, passing)
// ============================================================================
#define S2 136
#define XS_BYTES (128 * 136 * 2)
#define WCHUNK_U4 2048
#define SM2_BYTES (XS_BYTES + WCHUNK_U4 * 16)

__global__ __launch_bounds__(256)
void mlp_kernel(float* __restrict__ io,
                const float* __restrict__ ln2_s,
                const float* __restrict__ ln2_b,
                const float* __restrict__ fc1_b,
                const float* __restrict__ fc2_b)
{
    extern __shared__ char smem[];
    __nv_bfloat16* XS = (__nv_bfloat16*)smem;
    uint4* WB1 = (uint4*)(smem + XS_BYTES);
    uint4* WB2 = WB1 + 1024;

    const int tid  = threadIdx.x;
    const int lane = tid & 31;
    const int warp = tid >> 5;
    const size_t tok0 = (size_t)blockIdx.x * 128;

    const int r  = lane >> 2;
    const int c2 = (lane & 3) * 2;
    const int arow  = lane & 15;
    const int acol8 = (lane >> 4) * 8;

    {
        const int l = warp * 16 + (lane >> 1);
        const int q = lane & 1;
        const float* xp = io + (tok0 + l) * EDIM + q * 64;
        float v[64];
#pragma unroll
        for (int i = 0; i < 16; i++) {
            float4 t = reinterpret_cast<const float4*>(xp)[i];
            v[4*i] = t.x; v[4*i+1] = t.y; v[4*i+2] = t.z; v[4*i+3] = t.w;
        }
        float s1 = 0.f, s2 = 0.f;
#pragma unroll
        for (int i = 0; i < 64; i++) { s1 += v[i]; s2 += v[i] * v[i]; }
        s1 += __shfl_xor_sync(0xffffffffu, s1, 1);
        s2 += __shfl_xor_sync(0xffffffffu, s2, 1);
        const float mean = s1 * (1.f / 128.f);
        const float rstd = rsqrtf(s2 * (1.f / 128.f) - mean * mean + LN_EPS);
#pragma unroll
        for (int i = 0; i < 32; i++) {
            const int c = q * 64 + 2 * i;
            float a0 = (v[2*i]   - mean) * rstd * ln2_s[c]     + ln2_b[c];
            float a1 = (v[2*i+1] - mean) * rstd * ln2_s[c + 1] + ln2_b[c + 1];
            *(uint32_t*)&XS[l * S2 + c] = packbf(a0, a1);
        }
    }
    __syncwarp();

    uint32_t a[8][4];
#pragma unroll
    for (int kt = 0; kt < 8; kt++)
        ldmx4(a[kt], sa(&XS[(warp * 16 + arow) * S2 + kt * 16 + acol8]));

    float hacc[16][4];
#pragma unroll
    for (int j2 = 0; j2 < 16; j2++)
#pragma unroll
        for (int e = 0; e < 4; e++) hacc[j2][e] = 0.f;

    for (int nc = 0; nc < 8; nc++) {
        __syncthreads();
#pragma unroll
        for (int i = 0; i < 4; i++) {
            const int idx = i * 256 + tid;
            WB1[idx] = g_wfc1p[nc * 1024 + idx];
            WB2[idx] = g_wfc2p[nc * 1024 + idx];
        }
        __syncthreads();

        float c1[8][4];
#pragma unroll
        for (int j = 0; j < 8; j++)
#pragma unroll
            for (int e = 0; e < 4; e++) c1[j][e] = 0.f;
#pragma unroll
        for (int u = 0; u < 4; u++)
#pragma unroll
            for (int j = 0; j < 8; j++) {
                const uint4 B = WB1[(j * 4 + u) * 32 + lane];
                mma16816(c1[j], a[2*u],     B.x, B.y);
                mma16816(c1[j], a[2*u + 1], B.z, B.w);
            }

        uint32_t pa[4][4];
#pragma unroll
        for (int t = 0; t < 4; t++) {
#pragma unroll
            for (int p = 0; p < 2; p++) {
                const int j = 2 * t + p;
                const int gn = nc * 64 + j * 8 + c2;
                const float b0v = fc1_b[gn], b1v = fc1_b[gn + 1];
                float v0 = c1[j][0] + b0v, v1 = c1[j][1] + b1v;
                float v2 = c1[j][2] + b0v, v3 = c1[j][3] + b1v;
                v0 = 0.5f * v0 * (1.f + erff(v0 * 0.70710678118654752f));
                v1 = 0.5f * v1 * (1.f + erff(v1 * 0.70710678118654752f));
                v2 = 0.5f * v2 * (1.f + erff(v2 * 0.70710678118654752f));
                v3 = 0.5f * v3 * (1.f + erff(v3 * 0.70710678118654752f));
                pa[t][2*p]     = packbf(v0, v1);
                pa[t][2*p + 1] = packbf(v2, v3);
            }
        }

#pragma unroll
        for (int u2 = 0; u2 < 2; u2++)
#pragma unroll
            for (int j2 = 0; j2 < 16; j2++) {
                const uint4 B = WB2[(u2 * 16 + j2) * 32 + lane];
                mma16816(hacc[j2], pa[2*u2],     B.x, B.y);
                mma16816(hacc[j2], pa[2*u2 + 1], B.z, B.w);
            }
    }

    {
        float* base0 = io + (tok0 + warp * 16 + r) * EDIM;
        float* base1 = base0 + 8 * EDIM;
#pragma unroll
        for (int j2 = 0; j2 < 16; j2++) {
            const int col = j2 * 8 + c2;
            const float b0v = fc2_b[col], b1v = fc2_b[col + 1];
            float2 t0 = *(float2*)(base0 + col);
            t0.x += hacc[j2][0] + b0v;
            t0.y += hacc[j2][1] + b1v;
            *(float2*)(base0 + col) = t0;
            float2 t1 = *(float2*)(base1 + col);
            t1.x += hacc[j2][2] + b0v;
            t1.y += hacc[j2][3] + b1v;
            *(float2*)(base1 + col) = t1;
        }
    }
}

extern "C" void kernel_launch(void* const* d_in, const int* in_sizes, int n_in,
                              void* d_out, int out_size)
{
    const float* x      = (const float*)d_in[0];
    const float* qkv_w  = (const float*)d_in[1];
    const float* qkv_b  = (const float*)d_in[2];
    const float* proj_w = (const float*)d_in[3];
    const float* proj_b = (const float*)d_in[4];
    const float* ln1_s  = (const float*)d_in[5];
    const float* ln1_b  = (const float*)d_in[6];
    const float* ln2_s  = (const float*)d_in[7];
    const float* ln2_b  = (const float*)d_in[8];
    const float* fc1_w  = (const float*)d_in[9];
    const float* fc1_b  = (const float*)d_in[10];
    const float* fc2_w  = (const float*)d_in[11];
    const float* fc2_b  = (const float*)d_in[12];
    float* out = (float*)d_out;

    cudaFuncSetAttribute(attn_kernel, cudaFuncAttributeMaxDynamicSharedMemorySize, SM1_BYTES);
    cudaFuncSetAttribute(mlp_kernel,  cudaFuncAttributeMaxDynamicSharedMemorySize, SM2_BYTES);

    pack_qkvp<<<96, 256>>>(qkv_w);
    pack_projp<<<32, 256>>>(proj_w);
    conv_fc1p<<<128, 256>>>(fc1_w);
    conv_fc2p<<<128, 256>>>(fc2_w);
    attn_kernel<<<2048, 256, SM1_BYTES>>>(x, qkv_b, proj_b, ln1_s, ln1_b, out);
    mlp_kernel<<<2048, 256, SM2_BYTES>>>(out, ln2_s, ln2_b, fc1_b, fc2_b);
}